// round 6
// baseline (speedup 1.0000x reference)
#include <cuda_runtime.h>

// Problem constants
#define C_IN   384
#define NQKV   1152
#define MROWS  65536        // 1024 windows * 64 tokens
#define SHIFT_ 4

// Scratch (device globals; no allocation in kernel_launch)
__device__ float g_qkv[(size_t)MROWS * NQKV];   // 302 MB
__device__ float g_att[(size_t)MROWS * C_IN];   // 100 MB

// Map flattened window-token row m -> pixel base offset in the (B,64,64,384)
// image, applying the cyclic shift. Identical map for gather and scatter.
__device__ __forceinline__ int pix_base(int m) {
    int w  = m >> 6;        // window id: b*64 + wh*8 + ww
    int t  = m & 63;        // token id:  i*8 + j
    int b  = w >> 6;
    int wh = (w >> 3) & 7;
    int ww = w & 7;
    int i  = t >> 3;
    int j  = t & 7;
    int r  = (wh * 8 + i + SHIFT_) & 63;
    int c  = (ww * 8 + j + SHIFT_) & 63;
    return ((b * 64 + r) * 64 + c) * C_IN;
}

__device__ __forceinline__ unsigned f2tf32(float f) {
    unsigned r;
    asm("cvt.rna.tf32.f32 %0, %1;" : "=r"(r) : "f"(f));
    return r;
}

__device__ __forceinline__ void cp_async16(unsigned dst_smem, const void* src) {
    asm volatile("cp.async.cg.shared.global [%0], [%1], 16;"
                 :: "r"(dst_smem), "l"(src));
}

// Smem layouts (natural, padded for conflict-free fragment LDS):
// A[128][AST]: fragment bank = (4g+c)&31, all distinct for g in 0..7, c in 0..3
// B[16][BST] : fragment bank = (8c+g)&31, all distinct
#define KCH  16
#define AST  20
#define BST  136
#define ABUF (128*AST)   // 2560 words
#define BBUF (KCH*BST)   // 2176 words

// TF32 tensor-core GEMM: 128x128 tile, K-chunk 16, cp.async double buffer,
// 256 threads, 8 warps, warp tile 64x32 via mma.sync.m16n8k8.tf32.
template<int N, bool GATHER, bool SCATTER>
__global__ __launch_bounds__(256, 2) void gemm_tc(const float* __restrict__ X,
                                                  const float* __restrict__ W,
                                                  const float* __restrict__ bias,
                                                  float* __restrict__ Y)
{
    __shared__ float As[2][ABUF];
    __shared__ float Bs[2][BBUF];
    __shared__ int rowBase[128];
    __shared__ int outBase[128];

    const int tid = threadIdx.x;
    const int m0  = blockIdx.y * 128;
    const int n0  = blockIdx.x * 128;

    if (tid < 128) {
        int m = m0 + tid;
        rowBase[tid] = GATHER ? pix_base(m) : m * C_IN;
        if (SCATTER) outBase[tid] = pix_base(m);
    }
    __syncthreads();

    const float* Asrc = GATHER ? X : g_att;

    const int warp = tid >> 5, lane = tid & 31;
    const int wm = warp >> 2;   // 0..1  (64-row half)
    const int wn = warp & 3;    // 0..3  (32-col quarter)

    // Precomputed staging coordinates (2 A chunks + 2 B chunks per thread)
    const int amRow = tid >> 2;                 // A: idx 0..511 -> m = idx>>2
    const int akCol = (tid & 3) << 2;           //     k4 = (idx&3)*4
    const int bkRow = tid >> 5;                 // B: k = idx>>5
    const int bnCol = (tid & 31) << 2;          //     n4 = (idx&31)*4

    unsigned aDst0 = (unsigned)__cvta_generic_to_shared(&As[0][0]);
    unsigned bDst0 = (unsigned)__cvta_generic_to_shared(&Bs[0][0]);

    float acc[4][4][4];
    #pragma unroll
    for (int mi = 0; mi < 4; mi++)
        #pragma unroll
        for (int ni = 0; ni < 4; ni++)
            #pragma unroll
            for (int v = 0; v < 4; v++) acc[mi][ni][v] = 0.f;

    const int NIT = C_IN / KCH;   // 24

    // ---- stage one K-chunk into buffer buf ----
    auto stage = [&](int chunk, int buf) {
        int k0 = chunk * KCH;
        #pragma unroll
        for (int it = 0; it < 2; it++) {
            int m  = amRow + it * 64;
            cp_async16(aDst0 + (unsigned)((buf * ABUF + m * AST + akCol) * 4),
                       Asrc + rowBase[m] + k0 + akCol);
        }
        #pragma unroll
        for (int it = 0; it < 2; it++) {
            int k = bkRow + it * 8;
            cp_async16(bDst0 + (unsigned)((buf * BBUF + k * BST + bnCol) * 4),
                       W + (size_t)(k0 + k) * N + n0 + bnCol);
        }
        asm volatile("cp.async.commit_group;");
    };

    stage(0, 0);

    for (int itc = 0; itc < NIT; itc++) {
        asm volatile("cp.async.wait_group 0;");
        __syncthreads();
        if (itc + 1 < NIT) stage(itc + 1, (itc + 1) & 1);

        const float* Ab = As[itc & 1];
        const float* Bb = Bs[itc & 1];

        #pragma unroll
        for (int ki = 0; ki < 2; ki++) {
            unsigned af[4][4], bf[4][2];
            #pragma unroll
            for (int mi = 0; mi < 4; mi++) {
                const float* ap = Ab + (wm * 64 + mi * 16 + (lane >> 2)) * AST
                                     + ki * 8 + (lane & 3);
                af[mi][0] = f2tf32(ap[0]);
                af[mi][1] = f2tf32(ap[8 * AST]);
                af[mi][2] = f2tf32(ap[4]);
                af[mi][3] = f2tf32(ap[8 * AST + 4]);
            }
            #pragma unroll
            for (int ni = 0; ni < 4; ni++) {
                const float* bp = Bb + (ki * 8 + (lane & 3)) * BST
                                     + wn * 32 + ni * 8 + (lane >> 2);
                bf[ni][0] = f2tf32(bp[0]);
                bf[ni][1] = f2tf32(bp[4 * BST]);
            }
            #pragma unroll
            for (int mi = 0; mi < 4; mi++)
                #pragma unroll
                for (int ni = 0; ni < 4; ni++)
                    asm volatile(
                        "mma.sync.aligned.m16n8k8.row.col.f32.tf32.tf32.f32 "
                        "{%0,%1,%2,%3}, {%4,%5,%6,%7}, {%8,%9}, {%0,%1,%2,%3};"
                        : "+f"(acc[mi][ni][0]), "+f"(acc[mi][ni][1]),
                          "+f"(acc[mi][ni][2]), "+f"(acc[mi][ni][3])
                        : "r"(af[mi][0]), "r"(af[mi][1]), "r"(af[mi][2]), "r"(af[mi][3]),
                          "r"(bf[ni][0]), "r"(bf[ni][1]));
        }
        __syncthreads();
    }

    // ---- epilogue: bias + store (optionally scattered) ----
    float* Ydst = SCATTER ? Y : g_qkv;
    #pragma unroll
    for (int mi = 0; mi < 4; mi++) {
        int mrow = (wm * 4 + mi) * 16 + (lane >> 2);   // local row 0..127
        #pragma unroll
        for (int half = 0; half < 2; half++) {
            int ml = mrow + half * 8;
            size_t ob = SCATTER ? (size_t)outBase[ml] : (size_t)(m0 + ml) * N;
            #pragma unroll
            for (int ni = 0; ni < 4; ni++) {
                int n = n0 + (wn * 4 + ni) * 8 + (lane & 3) * 2;
                float2 b2 = *(const float2*)(bias + n);
                float2 val;
                val.x = acc[mi][ni][half * 2 + 0] + b2.x;
                val.y = acc[mi][ni][half * 2 + 1] + b2.y;
                *(float2*)(Ydst + ob + n) = val;
            }
        }
    }
}

// One block per (head, window). 64 threads; thread t owns score row t.
// Scores held in registers (all loops over s[] fully unrolled).
__global__ __launch_bounds__(64) void attn_kernel()
{
    const int h = blockIdx.x;   // 0..11
    const int w = blockIdx.y;   // 0..1023
    const int t = threadIdx.x;  // 0..63

    __shared__ float ks[64][36];   // padded to 36 (16B-aligned rows)
    __shared__ float vs[64][36];

    const float* base = g_qkv + (size_t)w * 64 * NQKV;
    const int qo = h * 32;
    const int ko = 384 + h * 32;
    const int vo = 768 + h * 32;

    for (int e = t; e < 64 * 32; e += 64) {
        int row = e >> 5, d = e & 31;
        ks[row][d] = base[row * NQKV + ko + d];
        vs[row][d] = base[row * NQKV + vo + d];
    }

    float4 q[8];
    #pragma unroll
    for (int d = 0; d < 8; d++)
        q[d] = *(const float4*)(base + t * NQKV + qo + d * 4);
    __syncthreads();

    // scores -> registers
    float s[64];
    #pragma unroll
    for (int j = 0; j < 64; j++) {
        float acc = 0.f;
        #pragma unroll
        for (int d = 0; d < 8; d++) {
            float4 kv = *(const float4*)&ks[j][d * 4];
            acc = fmaf(q[d].x, kv.x, acc);
            acc = fmaf(q[d].y, kv.y, acc);
            acc = fmaf(q[d].z, kv.z, acc);
            acc = fmaf(q[d].w, kv.w, acc);
        }
        s[j] = acc;
    }

    // softmax in registers (scale commutes with max)
    const float scale = 0.17677669529663687f;   // 1/sqrt(32)
    float mx = -1e30f;
    #pragma unroll
    for (int j = 0; j < 64; j++) mx = fmaxf(mx, s[j]);
    float sum = 0.f;
    #pragma unroll
    for (int j = 0; j < 64; j++) {
        float p = __expf((s[j] - mx) * scale);
        s[j] = p;
        sum += p;
    }
    float inv = 1.f / sum;

    // P @ V
    float4 o[8];
    #pragma unroll
    for (int d = 0; d < 8; d++) o[d] = make_float4(0.f, 0.f, 0.f, 0.f);
    #pragma unroll
    for (int j = 0; j < 64; j++) {
        float p = s[j];
        #pragma unroll
        for (int d = 0; d < 8; d++) {
            float4 vv = *(const float4*)&vs[j][d * 4];
            o[d].x = fmaf(p, vv.x, o[d].x);
            o[d].y = fmaf(p, vv.y, o[d].y);
            o[d].z = fmaf(p, vv.z, o[d].z);
            o[d].w = fmaf(p, vv.w, o[d].w);
        }
    }

    // stage output (reuse ks) for coalesced global store
    __syncthreads();
    #pragma unroll
    for (int d = 0; d < 8; d++) {
        ks[t][d * 4 + 0] = o[d].x * inv;
        ks[t][d * 4 + 1] = o[d].y * inv;
        ks[t][d * 4 + 2] = o[d].z * inv;
        ks[t][d * 4 + 3] = o[d].w * inv;
    }
    __syncthreads();

    float* obase = g_att + (size_t)w * 64 * C_IN + h * 32;
    for (int e = t; e < 64 * 32; e += 64) {
        int row = e >> 5, d = e & 31;
        obase[row * C_IN + d] = ks[row][d];
    }
}

extern "C" void kernel_launch(void* const* d_in, const int* in_sizes, int n_in,
                              void* d_out, int out_size)
{
    const float* x      = (const float*)d_in[0];
    const float* w_qkv  = (const float*)d_in[1];
    const float* b_qkv  = (const float*)d_in[2];
    const float* w_proj = (const float*)d_in[3];
    const float* b_proj = (const float*)d_in[4];
    float* out = (float*)d_out;

    // Stage 1: gathered QKV GEMM  (65536 x 1152 x 384), tf32 tensor cores
    gemm_tc<NQKV, true, false><<<dim3(9, 512), 256>>>(x, w_qkv, b_qkv, out);

    // Stage 2: window attention
    attn_kernel<<<dim3(12, 1024), 64>>>();

    // Stage 3: proj GEMM with scatter (65536 x 384 x 384), tf32 tensor cores
    gemm_tc<C_IN, false, true><<<dim3(3, 512), 256>>>(x, w_proj, b_proj, out);
}

// round 7
// speedup vs baseline: 1.4926x; 1.4926x over previous
#include <cuda_runtime.h>

typedef unsigned long long u64;

// Problem constants
#define C_IN   384
#define NQKV   1152
#define MROWS  65536        // 1024 windows * 64 tokens
#define SHIFT_ 4
#define NX     (16*64*64*384)   // 25,165,824

// Scratch (device globals; no allocation in kernel_launch)
__device__ float g_qkv[(size_t)MROWS * NQKV];   // 302 MB
__device__ float g_att[(size_t)MROWS * C_IN];   // 100 MB (tf32-rounded)
__device__ float g_xc[(size_t)NX];              // 100 MB tf32-rounded x
__device__ float g_wq[(size_t)C_IN * NQKV];     // tf32-rounded w_qkv
__device__ float g_wp[(size_t)C_IN * C_IN];     // tf32-rounded w_proj

__device__ __forceinline__ int pix_base(int m) {
    int w  = m >> 6;
    int t  = m & 63;
    int b  = w >> 6;
    int wh = (w >> 3) & 7;
    int ww = w & 7;
    int i  = t >> 3;
    int j  = t & 7;
    int r  = (wh * 8 + i + SHIFT_) & 63;
    int c  = (ww * 8 + j + SHIFT_) & 63;
    return ((b * 64 + r) * 64 + c) * C_IN;
}

__device__ __forceinline__ unsigned f2tf32(float f) {
    unsigned r;
    asm("cvt.rna.tf32.f32 %0, %1;" : "=r"(r) : "f"(f));
    return r;
}

__device__ __forceinline__ void cp_async16(unsigned dst_smem, const void* src) {
    asm volatile("cp.async.cg.shared.global [%0], [%1], 16;"
                 :: "r"(dst_smem), "l"(src));
}

// packed f32x2 helpers
__device__ __forceinline__ u64 fma2(u64 a, u64 b, u64 c) {
    u64 d; asm("fma.rn.f32x2 %0, %1, %2, %3;" : "=l"(d) : "l"(a), "l"(b), "l"(c));
    return d;
}
__device__ __forceinline__ u64 pack2(float lo, float hi) {
    u64 d; asm("mov.b64 %0, {%1, %2};" : "=l"(d) : "f"(lo), "f"(hi));
    return d;
}
__device__ __forceinline__ void unpack2(u64 v, float& lo, float& hi) {
    asm("mov.b64 {%0, %1}, %2;" : "=f"(lo), "=f"(hi) : "l"(v));
}

// ---- prep: round fp32 -> tf32 bits (vectorized grid-stride) ----
__global__ void cvt_tf32_kernel(const float* __restrict__ src,
                                float* __restrict__ dst, int n4)
{
    int i = blockIdx.x * blockDim.x + threadIdx.x;
    int stride = gridDim.x * blockDim.x;
    for (; i < n4; i += stride) {
        float4 v = ((const float4*)src)[i];
        v.x = __uint_as_float(f2tf32(v.x));
        v.y = __uint_as_float(f2tf32(v.y));
        v.z = __uint_as_float(f2tf32(v.z));
        v.w = __uint_as_float(f2tf32(v.w));
        ((float4*)dst)[i] = v;
    }
}

// Smem layouts (natural, padded for conflict-free fragment LDS):
// A[128][AST]: fragment bank = (4g+c)&31 all distinct; B[16][BST]: (8c+g)&31
#define KCH  16
#define AST  20
#define BST  136
#define ABUF (128*AST)
#define BBUF (KCH*BST)

// TF32 tensor-core GEMM: operands pre-rounded to tf32 -> no cvt in loop.
// STAGE1: A = gathered g_xc, B = g_wq, out -> g_qkv (linear)
// else  : A = g_att (linear), B = g_wp, out -> Y scattered
template<int N, bool STAGE1>
__global__ __launch_bounds__(256, 2) void gemm_tc(const float* __restrict__ bias,
                                                  float* __restrict__ Y)
{
    __shared__ float As[2][ABUF];
    __shared__ float Bs[2][BBUF];
    __shared__ int rowBase[128];
    __shared__ int outBase[128];

    const int tid = threadIdx.x;
    const int m0  = blockIdx.y * 128;
    const int n0  = blockIdx.x * 128;

    if (tid < 128) {
        int m = m0 + tid;
        rowBase[tid] = STAGE1 ? pix_base(m) : m * C_IN;
        if (!STAGE1) outBase[tid] = pix_base(m);
    }
    __syncthreads();

    const float* Asrc = STAGE1 ? g_xc : g_att;
    const float* W    = STAGE1 ? g_wq : g_wp;

    const int warp = tid >> 5, lane = tid & 31;
    const int wm = warp >> 2;
    const int wn = warp & 3;

    const int amRow = tid >> 2;
    const int akCol = (tid & 3) << 2;
    const int bkRow = tid >> 5;
    const int bnCol = (tid & 31) << 2;

    unsigned aDst0 = (unsigned)__cvta_generic_to_shared(&As[0][0]);
    unsigned bDst0 = (unsigned)__cvta_generic_to_shared(&Bs[0][0]);

    float acc[4][4][4];
    #pragma unroll
    for (int mi = 0; mi < 4; mi++)
        #pragma unroll
        for (int ni = 0; ni < 4; ni++)
            #pragma unroll
            for (int v = 0; v < 4; v++) acc[mi][ni][v] = 0.f;

    const int NIT = C_IN / KCH;   // 24

    auto stage = [&](int chunk, int buf) {
        int k0 = chunk * KCH;
        #pragma unroll
        for (int it = 0; it < 2; it++) {
            int m = amRow + it * 64;
            cp_async16(aDst0 + (unsigned)((buf * ABUF + m * AST + akCol) * 4),
                       Asrc + rowBase[m] + k0 + akCol);
        }
        #pragma unroll
        for (int it = 0; it < 2; it++) {
            int k = bkRow + it * 8;
            cp_async16(bDst0 + (unsigned)((buf * BBUF + k * BST + bnCol) * 4),
                       W + (size_t)(k0 + k) * N + n0 + bnCol);
        }
        asm volatile("cp.async.commit_group;");
    };

    stage(0, 0);

    for (int itc = 0; itc < NIT; itc++) {
        asm volatile("cp.async.wait_group 0;");
        __syncthreads();
        if (itc + 1 < NIT) stage(itc + 1, (itc + 1) & 1);

        const float* Ab = As[itc & 1];
        const float* Bb = Bs[itc & 1];

        #pragma unroll
        for (int ki = 0; ki < 2; ki++) {
            unsigned af[4][4], bf[4][2];
            #pragma unroll
            for (int mi = 0; mi < 4; mi++) {
                const float* ap = Ab + (wm * 64 + mi * 16 + (lane >> 2)) * AST
                                     + ki * 8 + (lane & 3);
                af[mi][0] = __float_as_uint(ap[0]);
                af[mi][1] = __float_as_uint(ap[8 * AST]);
                af[mi][2] = __float_as_uint(ap[4]);
                af[mi][3] = __float_as_uint(ap[8 * AST + 4]);
            }
            #pragma unroll
            for (int ni = 0; ni < 4; ni++) {
                const float* bp = Bb + (ki * 8 + (lane & 3)) * BST
                                     + wn * 32 + ni * 8 + (lane >> 2);
                bf[ni][0] = __float_as_uint(bp[0]);
                bf[ni][1] = __float_as_uint(bp[4 * BST]);
            }
            #pragma unroll
            for (int mi = 0; mi < 4; mi++)
                #pragma unroll
                for (int ni = 0; ni < 4; ni++)
                    asm volatile(
                        "mma.sync.aligned.m16n8k8.row.col.f32.tf32.tf32.f32 "
                        "{%0,%1,%2,%3}, {%4,%5,%6,%7}, {%8,%9}, {%0,%1,%2,%3};"
                        : "+f"(acc[mi][ni][0]), "+f"(acc[mi][ni][1]),
                          "+f"(acc[mi][ni][2]), "+f"(acc[mi][ni][3])
                        : "r"(af[mi][0]), "r"(af[mi][1]), "r"(af[mi][2]), "r"(af[mi][3]),
                          "r"(bf[ni][0]), "r"(bf[ni][1]));
        }
        __syncthreads();
    }

    float* Ydst = STAGE1 ? g_qkv : Y;
    #pragma unroll
    for (int mi = 0; mi < 4; mi++) {
        int mrow = (wm * 4 + mi) * 16 + (lane >> 2);
        #pragma unroll
        for (int half = 0; half < 2; half++) {
            int ml = mrow + half * 8;
            size_t ob = STAGE1 ? (size_t)(m0 + ml) * N : (size_t)outBase[ml];
            #pragma unroll
            for (int ni = 0; ni < 4; ni++) {
                int n = n0 + (wn * 4 + ni) * 8 + (lane & 3) * 2;
                float2 b2 = *(const float2*)(bias + n);
                float2 val;
                val.x = acc[mi][ni][half * 2 + 0] + b2.x;
                val.y = acc[mi][ni][half * 2 + 1] + b2.y;
                *(float2*)(Ydst + ob + n) = val;
            }
        }
    }
}

// One block per (head, window); thread t owns score row t. Packed f32x2 math.
// Writes tf32-rounded output so GEMM2 needs no conversion.
__global__ __launch_bounds__(64) void attn_kernel()
{
    const int h = blockIdx.x;
    const int w = blockIdx.y;
    const int t = threadIdx.x;

    __shared__ float ks[64][36];   // 144B rows, 16B aligned
    __shared__ float vs[64][36];

    const float* base = g_qkv + (size_t)w * 64 * NQKV;
    const int qo = h * 32;
    const int ko = 384 + h * 32;
    const int vo = 768 + h * 32;

    for (int e = t; e < 64 * 32; e += 64) {
        int row = e >> 5, d = e & 31;
        ks[row][d] = base[row * NQKV + ko + d];
        vs[row][d] = base[row * NQKV + vo + d];
    }

    // q row as 16 packed f32x2
    u64 q2[16];
    {
        const u64* qp = (const u64*)(base + t * NQKV + qo);
        #pragma unroll
        for (int d = 0; d < 16; d += 2) {
            ulonglong2 v = *(const ulonglong2*)(qp + d);
            q2[d] = v.x; q2[d + 1] = v.y;
        }
    }
    __syncthreads();

    // scores (two packed accumulators to break the dependence chain)
    float s[64];
    #pragma unroll
    for (int j = 0; j < 64; j++) {
        const u64* kp = (const u64*)&ks[j][0];
        u64 a0 = 0ull, a1 = 0ull;
        #pragma unroll
        for (int d = 0; d < 16; d += 4) {
            ulonglong2 v0 = *(const ulonglong2*)(kp + d);
            ulonglong2 v1 = *(const ulonglong2*)(kp + d + 2);
            a0 = fma2(q2[d + 0], v0.x, a0);
            a1 = fma2(q2[d + 1], v0.y, a1);
            a0 = fma2(q2[d + 2], v1.x, a0);
            a1 = fma2(q2[d + 3], v1.y, a1);
        }
        float x0, x1, y0, y1;
        unpack2(a0, x0, x1);
        unpack2(a1, y0, y1);
        s[j] = (x0 + x1) + (y0 + y1);
    }

    // softmax (scale commutes with max)
    const float scale = 0.17677669529663687f;   // 1/sqrt(32)
    float mx = -1e30f;
    #pragma unroll
    for (int j = 0; j < 64; j++) mx = fmaxf(mx, s[j]);
    float sum = 0.f;
    #pragma unroll
    for (int j = 0; j < 64; j++) {
        float p = __expf((s[j] - mx) * scale);
        s[j] = p;
        sum += p;
    }
    float inv = 1.f / sum;

    // P @ V, packed
    u64 o2[16];
    #pragma unroll
    for (int d = 0; d < 16; d++) o2[d] = 0ull;
    #pragma unroll
    for (int j = 0; j < 64; j++) {
        u64 pp = pack2(s[j], s[j]);
        const u64* vp = (const u64*)&vs[j][0];
        #pragma unroll
        for (int d = 0; d < 16; d += 2) {
            ulonglong2 v = *(const ulonglong2*)(vp + d);
            o2[d + 0] = fma2(pp, v.x, o2[d + 0]);
            o2[d + 1] = fma2(pp, v.y, o2[d + 1]);
        }
    }

    // stage tf32-rounded output (reuse ks) for coalesced store
    __syncthreads();
    #pragma unroll
    for (int d = 0; d < 16; d++) {
        float a, b;
        unpack2(o2[d], a, b);
        ks[t][d * 2 + 0] = __uint_as_float(f2tf32(a * inv));
        ks[t][d * 2 + 1] = __uint_as_float(f2tf32(b * inv));
    }
    __syncthreads();

    float* obase = g_att + (size_t)w * 64 * C_IN + h * 32;
    for (int e = t; e < 64 * 32; e += 64) {
        int row = e >> 5, d = e & 31;
        obase[row * C_IN + d] = ks[row][d];
    }
}

extern "C" void kernel_launch(void* const* d_in, const int* in_sizes, int n_in,
                              void* d_out, int out_size)
{
    const float* x      = (const float*)d_in[0];
    const float* w_qkv  = (const float*)d_in[1];
    const float* b_qkv  = (const float*)d_in[2];
    const float* w_proj = (const float*)d_in[3];
    const float* b_proj = (const float*)d_in[4];
    float* out = (float*)d_out;

    float* d_xc; cudaGetSymbolAddress((void**)&d_xc, g_xc);
    float* d_wq; cudaGetSymbolAddress((void**)&d_wq, g_wq);
    float* d_wp; cudaGetSymbolAddress((void**)&d_wp, g_wp);

    // Stage 0: pre-round operands to tf32
    cvt_tf32_kernel<<<2048, 256>>>(x, d_xc, NX / 4);
    cvt_tf32_kernel<<<256, 256>>>(w_qkv, d_wq, (C_IN * NQKV) / 4);
    cvt_tf32_kernel<<<128, 256>>>(w_proj, d_wp, (C_IN * C_IN) / 4);

    // Stage 1: gathered QKV GEMM  (65536 x 1152 x 384)
    gemm_tc<NQKV, true><<<dim3(9, 512), 256>>>(b_qkv, out);

    // Stage 2: window attention
    attn_kernel<<<dim3(12, 1024), 64>>>();

    // Stage 3: proj GEMM with scatter (65536 x 384 x 384)
    gemm_tc<C_IN, false><<<dim3(3, 512), 256>>>(b_proj, out);
}

// round 9
// speedup vs baseline: 1.6230x; 1.0874x over previous
#include <cuda_runtime.h>

typedef unsigned long long u64;

// Problem constants
#define C_IN   384
#define NQKV   1152
#define MROWS  65536        // 1024 windows * 64 tokens
#define SHIFT_ 4
#define NX     (16*64*64*384)   // 25,165,824

// Scratch (device globals; no allocation in kernel_launch)
__device__ float g_qkv[(size_t)MROWS * NQKV];   // 302 MB
__device__ float g_att[(size_t)MROWS * C_IN];   // 100 MB (tf32-rounded)
__device__ float g_xc[(size_t)NX];              // 100 MB tf32-rounded x
__device__ float g_wq[(size_t)C_IN * NQKV];     // tf32-rounded w_qkv
__device__ float g_wp[(size_t)C_IN * C_IN];     // tf32-rounded w_proj

__device__ __forceinline__ int pix_base(int m) {
    int w  = m >> 6;
    int t  = m & 63;
    int b  = w >> 6;
    int wh = (w >> 3) & 7;
    int ww = w & 7;
    int i  = t >> 3;
    int j  = t & 7;
    int r  = (wh * 8 + i + SHIFT_) & 63;
    int c  = (ww * 8 + j + SHIFT_) & 63;
    return ((b * 64 + r) * 64 + c) * C_IN;
}

__device__ __forceinline__ unsigned f2tf32(float f) {
    unsigned r;
    asm("cvt.rna.tf32.f32 %0, %1;" : "=r"(r) : "f"(f));
    return r;
}

__device__ __forceinline__ void cp_async16(unsigned dst_smem, const void* src) {
    asm volatile("cp.async.cg.shared.global [%0], [%1], 16;"
                 :: "r"(dst_smem), "l"(src));
}

// packed f32x2 helpers
__device__ __forceinline__ u64 fma2(u64 a, u64 b, u64 c) {
    u64 d; asm("fma.rn.f32x2 %0, %1, %2, %3;" : "=l"(d) : "l"(a), "l"(b), "l"(c));
    return d;
}
__device__ __forceinline__ u64 pack2(float lo, float hi) {
    u64 d; asm("mov.b64 %0, {%1, %2};" : "=l"(d) : "f"(lo), "f"(hi));
    return d;
}
__device__ __forceinline__ void unpack2(u64 v, float& lo, float& hi) {
    asm("mov.b64 {%0, %1}, %2;" : "=f"(lo), "=f"(hi) : "l"(v));
}

// ---- prep: round fp32 -> tf32 bits (vectorized grid-stride) ----
__global__ void cvt_tf32_kernel(const float* __restrict__ src,
                                float* __restrict__ dst, int n4)
{
    int i = blockIdx.x * blockDim.x + threadIdx.x;
    int stride = gridDim.x * blockDim.x;
    for (; i < n4; i += stride) {
        float4 v = ((const float4*)src)[i];
        v.x = __uint_as_float(f2tf32(v.x));
        v.y = __uint_as_float(f2tf32(v.y));
        v.z = __uint_as_float(f2tf32(v.z));
        v.w = __uint_as_float(f2tf32(v.w));
        ((float4*)dst)[i] = v;
    }
}

// Smem layouts (natural, padded for conflict-free fragment LDS):
// A[128][36]: fragment bank = ((lane>>2)*4 + (lane&3)) = lane -> all distinct
// B[32][136]: fragment bank = (8c+g)&31 -> all distinct
#define KCH  32
#define AST  36
#define BST  136
#define ABUF (128*AST)             // 4608 words
#define BBUF (KCH*BST)             // 4352 words
#define SMEM_DYN ((2*ABUF + 2*BBUF) * 4)   // 71680 bytes

// TF32 tensor-core GEMM: operands pre-rounded to tf32 -> no cvt in loop.
// 128x128 tile, K-chunk 32 (12 iterations, 64 MMA/warp per barrier pair),
// cp.async double buffer in dynamic smem.
template<int N, bool STAGE1>
__global__ __launch_bounds__(256, 2) void gemm_tc(const float* __restrict__ bias,
                                                  float* __restrict__ Y)
{
    extern __shared__ float dsm[];
    float* Asm = dsm;                 // 2 * ABUF
    float* Bsm = dsm + 2 * ABUF;      // 2 * BBUF
    __shared__ int rowBase[128];
    __shared__ int outBase[128];

    const int tid = threadIdx.x;
    const int m0  = blockIdx.y * 128;
    const int n0  = blockIdx.x * 128;

    if (tid < 128) {
        int m = m0 + tid;
        rowBase[tid] = STAGE1 ? pix_base(m) : m * C_IN;
        if (!STAGE1) outBase[tid] = pix_base(m);
    }
    __syncthreads();

    const float* Asrc = STAGE1 ? g_xc : g_att;
    const float* W    = STAGE1 ? g_wq : g_wp;

    const int warp = tid >> 5, lane = tid & 31;
    const int wm = warp >> 2;
    const int wn = warp & 3;

    // staging coords: 4 A float4s + 4 B float4s per thread per chunk
    const int amRow = tid >> 3;                 // + it*32
    const int akCol = (tid & 7) << 2;
    const int bkRow = tid >> 5;                 // + it*8
    const int bnCol = (tid & 31) << 2;

    unsigned aDst0 = (unsigned)__cvta_generic_to_shared(Asm);
    unsigned bDst0 = (unsigned)__cvta_generic_to_shared(Bsm);

    float acc[4][4][4];
    #pragma unroll
    for (int mi = 0; mi < 4; mi++)
        #pragma unroll
        for (int ni = 0; ni < 4; ni++)
            #pragma unroll
            for (int v = 0; v < 4; v++) acc[mi][ni][v] = 0.f;

    const int NIT = C_IN / KCH;   // 12

    auto stage = [&](int chunk, int buf) {
        int k0 = chunk * KCH;
        #pragma unroll
        for (int it = 0; it < 4; it++) {
            int m = amRow + it * 32;
            cp_async16(aDst0 + (unsigned)((buf * ABUF + m * AST + akCol) * 4),
                       Asrc + rowBase[m] + k0 + akCol);
        }
        #pragma unroll
        for (int it = 0; it < 4; it++) {
            int k = bkRow + it * 8;
            cp_async16(bDst0 + (unsigned)((buf * BBUF + k * BST + bnCol) * 4),
                       W + (size_t)(k0 + k) * N + n0 + bnCol);
        }
        asm volatile("cp.async.commit_group;");
    };

    stage(0, 0);

    for (int itc = 0; itc < NIT; itc++) {
        asm volatile("cp.async.wait_group 0;");
        __syncthreads();
        if (itc + 1 < NIT) stage(itc + 1, (itc + 1) & 1);

        const float* Ab = Asm + (itc & 1) * ABUF;
        const float* Bb = Bsm + (itc & 1) * BBUF;

        #pragma unroll
        for (int ki = 0; ki < 4; ki++) {
            unsigned af[4][4], bf[4][2];
            #pragma unroll
            for (int mi = 0; mi < 4; mi++) {
                const float* ap = Ab + (wm * 64 + mi * 16 + (lane >> 2)) * AST
                                     + ki * 8 + (lane & 3);
                af[mi][0] = __float_as_uint(ap[0]);
                af[mi][1] = __float_as_uint(ap[8 * AST]);
                af[mi][2] = __float_as_uint(ap[4]);
                af[mi][3] = __float_as_uint(ap[8 * AST + 4]);
            }
            #pragma unroll
            for (int ni = 0; ni < 4; ni++) {
                const float* bp = Bb + (ki * 8 + (lane & 3)) * BST
                                     + wn * 32 + ni * 8 + (lane >> 2);
                bf[ni][0] = __float_as_uint(bp[0]);
                bf[ni][1] = __float_as_uint(bp[4 * BST]);
            }
            #pragma unroll
            for (int mi = 0; mi < 4; mi++)
                #pragma unroll
                for (int ni = 0; ni < 4; ni++)
                    asm volatile(
                        "mma.sync.aligned.m16n8k8.row.col.f32.tf32.tf32.f32 "
                        "{%0,%1,%2,%3}, {%4,%5,%6,%7}, {%8,%9}, {%0,%1,%2,%3};"
                        : "+f"(acc[mi][ni][0]), "+f"(acc[mi][ni][1]),
                          "+f"(acc[mi][ni][2]), "+f"(acc[mi][ni][3])
                        : "r"(af[mi][0]), "r"(af[mi][1]), "r"(af[mi][2]), "r"(af[mi][3]),
                          "r"(bf[ni][0]), "r"(bf[ni][1]));
        }
        __syncthreads();
    }

    float* Ydst = STAGE1 ? g_qkv : Y;
    #pragma unroll
    for (int mi = 0; mi < 4; mi++) {
        int mrow = (wm * 4 + mi) * 16 + (lane >> 2);
        #pragma unroll
        for (int half = 0; half < 2; half++) {
            int ml = mrow + half * 8;
            size_t ob = STAGE1 ? (size_t)(m0 + ml) * N : (size_t)outBase[ml];
            #pragma unroll
            for (int ni = 0; ni < 4; ni++) {
                int n = n0 + (wn * 4 + ni) * 8 + (lane & 3) * 2;
                float2 b2 = *(const float2*)(bias + n);
                float2 val;
                val.x = acc[mi][ni][half * 2 + 0] + b2.x;
                val.y = acc[mi][ni][half * 2 + 1] + b2.y;
                *(float2*)(Ydst + ob + n) = val;
            }
        }
    }
}

// One block per (head, window); thread t owns score row t. Packed f32x2 math.
// Writes tf32-rounded output so GEMM2 needs no conversion.
__global__ __launch_bounds__(64) void attn_kernel()
{
    const int h = blockIdx.x;
    const int w = blockIdx.y;
    const int t = threadIdx.x;

    __shared__ float ks[64][36];
    __shared__ float vs[64][36];

    const float* base = g_qkv + (size_t)w * 64 * NQKV;
    const int qo = h * 32;
    const int ko = 384 + h * 32;
    const int vo = 768 + h * 32;

    for (int e = t; e < 64 * 32; e += 64) {
        int row = e >> 5, d = e & 31;
        ks[row][d] = base[row * NQKV + ko + d];
        vs[row][d] = base[row * NQKV + vo + d];
    }

    u64 q2[16];
    {
        const u64* qp = (const u64*)(base + t * NQKV + qo);
        #pragma unroll
        for (int d = 0; d < 16; d += 2) {
            ulonglong2 v = *(const ulonglong2*)(qp + d);
            q2[d] = v.x; q2[d + 1] = v.y;
        }
    }
    __syncthreads();

    float s[64];
    #pragma unroll
    for (int j = 0; j < 64; j++) {
        const u64* kp = (const u64*)&ks[j][0];
        u64 a0 = 0ull, a1 = 0ull;
        #pragma unroll
        for (int d = 0; d < 16; d += 4) {
            ulonglong2 v0 = *(const ulonglong2*)(kp + d);
            ulonglong2 v1 = *(const ulonglong2*)(kp + d + 2);
            a0 = fma2(q2[d + 0], v0.x, a0);
            a1 = fma2(q2[d + 1], v0.y, a1);
            a0 = fma2(q2[d + 2], v1.x, a0);
            a1 = fma2(q2[d + 3], v1.y, a1);
        }
        float x0, x1, y0, y1;
        unpack2(a0, x0, x1);
        unpack2(a1, y0, y1);
        s[j] = (x0 + x1) + (y0 + y1);
    }

    const float scale = 0.17677669529663687f;   // 1/sqrt(32)
    float mx = -1e30f;
    #pragma unroll
    for (int j = 0; j < 64; j++) mx = fmaxf(mx, s[j]);
    float sum = 0.f;
    #pragma unroll
    for (int j = 0; j < 64; j++) {
        float p = __expf((s[j] - mx) * scale);
        s[j] = p;
        sum += p;
    }
    float inv = 1.f / sum;

    u64 o2[16];
    #pragma unroll
    for (int d = 0; d < 16; d++) o2[d] = 0ull;
    #pragma unroll
    for (int j = 0; j < 64; j++) {
        u64 pp = pack2(s[j], s[j]);
        const u64* vp = (const u64*)&vs[j][0];
        #pragma unroll
        for (int d = 0; d < 16; d += 2) {
            ulonglong2 v = *(const ulonglong2*)(vp + d);
            o2[d + 0] = fma2(pp, v.x, o2[d + 0]);
            o2[d + 1] = fma2(pp, v.y, o2[d + 1]);
        }
    }

    __syncthreads();
    #pragma unroll
    for (int d = 0; d < 16; d++) {
        float a, b;
        unpack2(o2[d], a, b);
        ks[t][d * 2 + 0] = __uint_as_float(f2tf32(a * inv));
        ks[t][d * 2 + 1] = __uint_as_float(f2tf32(b * inv));
    }
    __syncthreads();

    float* obase = g_att + (size_t)w * 64 * C_IN + h * 32;
    for (int e = t; e < 64 * 32; e += 64) {
        int row = e >> 5, d = e & 31;
        obase[row * C_IN + d] = ks[row][d];
    }
}

extern "C" void kernel_launch(void* const* d_in, const int* in_sizes, int n_in,
                              void* d_out, int out_size)
{
    const float* x      = (const float*)d_in[0];
    const float* w_qkv  = (const float*)d_in[1];
    const float* b_qkv  = (const float*)d_in[2];
    const float* w_proj = (const float*)d_in[3];
    const float* b_proj = (const float*)d_in[4];
    float* out = (float*)d_out;

    float* d_xc; cudaGetSymbolAddress((void**)&d_xc, g_xc);
    float* d_wq; cudaGetSymbolAddress((void**)&d_wq, g_wq);
    float* d_wp; cudaGetSymbolAddress((void**)&d_wp, g_wp);

    cudaFuncSetAttribute(gemm_tc<NQKV, true>,
                         cudaFuncAttributeMaxDynamicSharedMemorySize, SMEM_DYN);
    cudaFuncSetAttribute(gemm_tc<C_IN, false>,
                         cudaFuncAttributeMaxDynamicSharedMemorySize, SMEM_DYN);

    // Stage 0: pre-round operands to tf32
    cvt_tf32_kernel<<<2048, 256>>>(x, d_xc, NX / 4);
    cvt_tf32_kernel<<<256, 256>>>(w_qkv, d_wq, (C_IN * NQKV) / 4);
    cvt_tf32_kernel<<<128, 256>>>(w_proj, d_wp, (C_IN * C_IN) / 4);

    // Stage 1: gathered QKV GEMM  (65536 x 1152 x 384)
    gemm_tc<NQKV, true><<<dim3(9, 512), 256, SMEM_DYN>>>(b_qkv, out);

    // Stage 2: window attention
    attn_kernel<<<dim3(12, 1024), 64>>>();

    // Stage 3: proj GEMM with scatter (65536 x 384 x 384)
    gemm_tc<C_IN, false><<<dim3(3, 512), 256, SMEM_DYN>>>(b_proj, out);
}

// round 11
// speedup vs baseline: 1.7296x; 1.0657x over previous
#include <cuda_runtime.h>

typedef unsigned long long u64;

// Problem constants
#define C_IN   384
#define NQKV   1152
#define MROWS  65536        // 1024 windows * 64 tokens
#define SHIFT_ 4
#define NX     (16*64*64*384)   // 25,165,824

// Scratch (device globals; no allocation in kernel_launch)
__device__ float g_qkv[(size_t)MROWS * NQKV];   // 302 MB
__device__ float g_att[(size_t)MROWS * C_IN];   // 100 MB (tf32-rounded)
__device__ float g_xc[(size_t)NX];              // 100 MB tf32-rounded x
__device__ float g_wq[(size_t)C_IN * NQKV];     // tf32-rounded w_qkv
__device__ float g_wp[(size_t)C_IN * C_IN];     // tf32-rounded w_proj

__device__ __forceinline__ int pix_base(int m) {
    int w  = m >> 6;
    int t  = m & 63;
    int b  = w >> 6;
    int wh = (w >> 3) & 7;
    int ww = w & 7;
    int i  = t >> 3;
    int j  = t & 7;
    int r  = (wh * 8 + i + SHIFT_) & 63;
    int c  = (ww * 8 + j + SHIFT_) & 63;
    return ((b * 64 + r) * 64 + c) * C_IN;
}

__device__ __forceinline__ unsigned f2tf32(float f) {
    unsigned r;
    asm("cvt.rna.tf32.f32 %0, %1;" : "=r"(r) : "f"(f));
    return r;
}
__device__ __forceinline__ float rnd(float f) {
    return __uint_as_float(f2tf32(f));
}

__device__ __forceinline__ void cp_async16(unsigned dst_smem, const void* src) {
    asm volatile("cp.async.cg.shared.global [%0], [%1], 16;"
                 :: "r"(dst_smem), "l"(src));
}

__device__ __forceinline__ void mma_tf32(float* d, unsigned a0, unsigned a1,
                                         unsigned a2, unsigned a3,
                                         unsigned b0, unsigned b1) {
    asm volatile(
        "mma.sync.aligned.m16n8k8.row.col.f32.tf32.tf32.f32 "
        "{%0,%1,%2,%3}, {%4,%5,%6,%7}, {%8,%9}, {%0,%1,%2,%3};"
        : "+f"(d[0]), "+f"(d[1]), "+f"(d[2]), "+f"(d[3])
        : "r"(a0), "r"(a1), "r"(a2), "r"(a3), "r"(b0), "r"(b1));
}

// ---- prep: round fp32 -> tf32 bits (vectorized grid-stride) ----
__global__ void cvt_tf32_kernel(const float* __restrict__ src,
                                float* __restrict__ dst, int n4)
{
    int i = blockIdx.x * blockDim.x + threadIdx.x;
    int stride = gridDim.x * blockDim.x;
    for (; i < n4; i += stride) {
        float4 v = ((const float4*)src)[i];
        v.x = rnd(v.x); v.y = rnd(v.y); v.z = rnd(v.z); v.w = rnd(v.w);
        ((float4*)dst)[i] = v;
    }
}

// Smem layouts (natural, padded for conflict-free fragment LDS):
// A[128][36]: fragment bank = ((lane>>2)*4 + (lane&3)) = lane -> all distinct
// B[32][136]: fragment bank = (8c+g)&31 -> all distinct
#define KCH  32
#define AST  36
#define BST  136
#define ABUF (128*AST)             // 4608 words
#define BBUF (KCH*BST)             // 4352 words
#define SMEM_DYN ((2*ABUF + 2*BBUF) * 4)   // 71680 bytes

template<int N, bool STAGE1>
__global__ __launch_bounds__(256, 2) void gemm_tc(const float* __restrict__ bias,
                                                  float* __restrict__ Y)
{
    extern __shared__ float dsm[];
    float* Asm = dsm;
    float* Bsm = dsm + 2 * ABUF;
    __shared__ int rowBase[128];
    __shared__ int outBase[128];

    const int tid = threadIdx.x;
    const int m0  = blockIdx.y * 128;
    const int n0  = blockIdx.x * 128;

    if (tid < 128) {
        int m = m0 + tid;
        rowBase[tid] = STAGE1 ? pix_base(m) : m * C_IN;
        if (!STAGE1) outBase[tid] = pix_base(m);
    }
    __syncthreads();

    const float* Asrc = STAGE1 ? g_xc : g_att;
    const float* W    = STAGE1 ? g_wq : g_wp;

    const int warp = tid >> 5, lane = tid & 31;
    const int wm = warp >> 2;
    const int wn = warp & 3;

    const int amRow = tid >> 3;
    const int akCol = (tid & 7) << 2;
    const int bkRow = tid >> 5;
    const int bnCol = (tid & 31) << 2;

    unsigned aDst0 = (unsigned)__cvta_generic_to_shared(Asm);
    unsigned bDst0 = (unsigned)__cvta_generic_to_shared(Bsm);

    float acc[4][4][4];
    #pragma unroll
    for (int mi = 0; mi < 4; mi++)
        #pragma unroll
        for (int ni = 0; ni < 4; ni++)
            #pragma unroll
            for (int v = 0; v < 4; v++) acc[mi][ni][v] = 0.f;

    const int NIT = C_IN / KCH;   // 12

    auto stage = [&](int chunk, int buf) {
        int k0 = chunk * KCH;
        #pragma unroll
        for (int it = 0; it < 4; it++) {
            int m = amRow + it * 32;
            cp_async16(aDst0 + (unsigned)((buf * ABUF + m * AST + akCol) * 4),
                       Asrc + rowBase[m] + k0 + akCol);
        }
        #pragma unroll
        for (int it = 0; it < 4; it++) {
            int k = bkRow + it * 8;
            cp_async16(bDst0 + (unsigned)((buf * BBUF + k * BST + bnCol) * 4),
                       W + (size_t)(k0 + k) * N + n0 + bnCol);
        }
        asm volatile("cp.async.commit_group;");
    };

    stage(0, 0);

    for (int itc = 0; itc < NIT; itc++) {
        asm volatile("cp.async.wait_group 0;");
        __syncthreads();
        if (itc + 1 < NIT) stage(itc + 1, (itc + 1) & 1);

        const float* Ab = Asm + (itc & 1) * ABUF;
        const float* Bb = Bsm + (itc & 1) * BBUF;

        #pragma unroll
        for (int ki = 0; ki < 4; ki++) {
            unsigned af[4][4], bf[4][2];
            #pragma unroll
            for (int mi = 0; mi < 4; mi++) {
                const float* ap = Ab + (wm * 64 + mi * 16 + (lane >> 2)) * AST
                                     + ki * 8 + (lane & 3);
                af[mi][0] = __float_as_uint(ap[0]);
                af[mi][1] = __float_as_uint(ap[8 * AST]);
                af[mi][2] = __float_as_uint(ap[4]);
                af[mi][3] = __float_as_uint(ap[8 * AST + 4]);
            }
            #pragma unroll
            for (int ni = 0; ni < 4; ni++) {
                const float* bp = Bb + (ki * 8 + (lane & 3)) * BST
                                     + wn * 32 + ni * 8 + (lane >> 2);
                bf[ni][0] = __float_as_uint(bp[0]);
                bf[ni][1] = __float_as_uint(bp[4 * BST]);
            }
            #pragma unroll
            for (int mi = 0; mi < 4; mi++)
                #pragma unroll
                for (int ni = 0; ni < 4; ni++)
                    mma_tf32(acc[mi][ni], af[mi][0], af[mi][1], af[mi][2],
                             af[mi][3], bf[ni][0], bf[ni][1]);
        }
        __syncthreads();
    }

    float* Ydst = STAGE1 ? g_qkv : Y;
    #pragma unroll
    for (int mi = 0; mi < 4; mi++) {
        int mrow = (wm * 4 + mi) * 16 + (lane >> 2);
        #pragma unroll
        for (int half = 0; half < 2; half++) {
            int ml = mrow + half * 8;
            size_t ob = STAGE1 ? (size_t)(m0 + ml) * N : (size_t)outBase[ml];
            #pragma unroll
            for (int ni = 0; ni < 4; ni++) {
                int n = n0 + (wn * 4 + ni) * 8 + (lane & 3) * 2;
                float2 b2 = *(const float2*)(bias + n);
                float2 val;
                val.x = acc[mi][ni][half * 2 + 0] + b2.x;
                val.y = acc[mi][ni][half * 2 + 1] + b2.y;
                *(float2*)(Ydst + ob + n) = val;
            }
        }
    }
}

// ---- MMA attention: one warp per (window, head), 4 warps per block ----
// Warp-private smem: Ksm[32][72] (K^T, stride%32=8 -> B-frag conflict-free),
// Vsm[64][40] (stride%32=8), Ps[16][68] (stride%32=4 -> A-frag conflict-free).
#define KT_ST 72
#define V_ST  40
#define P_ST  68
#define WSL   (32*KT_ST + 64*V_ST + 16*P_ST)   // 5952 words per warp
#define ATT_SMEM (4 * WSL * 4)                 // 95232 bytes

__global__ __launch_bounds__(128) void attn_mma()
{
    extern __shared__ float sm[];
    const int warp = threadIdx.x >> 5, lane = threadIdx.x & 31;
    const int id = blockIdx.x * 4 + warp;    // 0..12287
    const int w = id / 12, h = id - w * 12;

    float* Ksm = sm + warp * WSL;
    float* Vsm = Ksm + 32 * KT_ST;
    float* Ps  = Vsm + 64 * V_ST;

    const float* base = g_qkv + (size_t)w * 64 * NQKV;
    const int qo = h * 32, ko = 384 + h * 32, vo = 768 + h * 32;

    // stage K transposed + V natural, tf32-rounded
    for (int e = lane; e < 512; e += 32) {
        int tok = e >> 3, d4 = (e & 7) << 2;
        float4 kv = *(const float4*)(base + tok * NQKV + ko + d4);
        Ksm[(d4 + 0) * KT_ST + tok] = rnd(kv.x);
        Ksm[(d4 + 1) * KT_ST + tok] = rnd(kv.y);
        Ksm[(d4 + 2) * KT_ST + tok] = rnd(kv.z);
        Ksm[(d4 + 3) * KT_ST + tok] = rnd(kv.w);
        float4 vv = *(const float4*)(base + tok * NQKV + vo + d4);
        vv.x = rnd(vv.x); vv.y = rnd(vv.y); vv.z = rnd(vv.z); vv.w = rnd(vv.w);
        *(float4*)&Vsm[tok * V_ST + d4] = vv;
    }
    __syncwarp();

    const int g = lane >> 2, c = lane & 3;
    const float scale = 0.17677669529663687f;   // 1/sqrt(32)
    float* obh = g_att + (size_t)w * 64 * C_IN + h * 32;

    for (int mi = 0; mi < 4; mi++) {
        // ---- S = Q @ K^T  (m16 x n64, k32) ----
        float s[8][4];
        #pragma unroll
        for (int ni = 0; ni < 8; ni++)
            #pragma unroll
            for (int v = 0; v < 4; v++) s[ni][v] = 0.f;

        #pragma unroll
        for (int ki = 0; ki < 4; ki++) {
            const float* qp = base + (mi * 16 + g) * NQKV + qo + ki * 8 + c;
            unsigned a0 = f2tf32(qp[0]);
            unsigned a1 = f2tf32(qp[8 * NQKV]);
            unsigned a2 = f2tf32(qp[4]);
            unsigned a3 = f2tf32(qp[8 * NQKV + 4]);
            #pragma unroll
            for (int ni = 0; ni < 8; ni++) {
                const float* bp = Ksm + (ki * 8 + c) * KT_ST + ni * 8 + g;
                mma_tf32(s[ni], a0, a1, a2, a3,
                         __float_as_uint(bp[0]), __float_as_uint(bp[4 * KT_ST]));
            }
        }

        // ---- softmax over the two rows this thread covers ----
        float mA = -1e30f, mB = -1e30f;
        #pragma unroll
        for (int ni = 0; ni < 8; ni++) {
            mA = fmaxf(mA, fmaxf(s[ni][0], s[ni][1]));
            mB = fmaxf(mB, fmaxf(s[ni][2], s[ni][3]));
        }
        mA = fmaxf(mA, __shfl_xor_sync(0xffffffff, mA, 1));
        mA = fmaxf(mA, __shfl_xor_sync(0xffffffff, mA, 2));
        mB = fmaxf(mB, __shfl_xor_sync(0xffffffff, mB, 1));
        mB = fmaxf(mB, __shfl_xor_sync(0xffffffff, mB, 2));

        float sumA = 0.f, sumB = 0.f;
        #pragma unroll
        for (int ni = 0; ni < 8; ni++) {
            s[ni][0] = __expf((s[ni][0] - mA) * scale);
            s[ni][1] = __expf((s[ni][1] - mA) * scale);
            s[ni][2] = __expf((s[ni][2] - mB) * scale);
            s[ni][3] = __expf((s[ni][3] - mB) * scale);
            sumA += s[ni][0] + s[ni][1];
            sumB += s[ni][2] + s[ni][3];
        }
        sumA += __shfl_xor_sync(0xffffffff, sumA, 1);
        sumA += __shfl_xor_sync(0xffffffff, sumA, 2);
        sumB += __shfl_xor_sync(0xffffffff, sumB, 1);
        sumB += __shfl_xor_sync(0xffffffff, sumB, 2);
        float invA = 1.f / sumA, invB = 1.f / sumB;

        // ---- normalized, tf32-rounded P -> smem ----
        __syncwarp();   // previous pass's PV reads of Ps are done
        #pragma unroll
        for (int ni = 0; ni < 8; ni++) {
            int col = ni * 8 + c * 2;
            Ps[g * P_ST + col]           = rnd(s[ni][0] * invA);
            Ps[g * P_ST + col + 1]       = rnd(s[ni][1] * invA);
            Ps[(g + 8) * P_ST + col]     = rnd(s[ni][2] * invB);
            Ps[(g + 8) * P_ST + col + 1] = rnd(s[ni][3] * invB);
        }
        __syncwarp();

        // ---- O = P @ V  (m16 x n32, k64) ----
        float o[4][4];
        #pragma unroll
        for (int ni = 0; ni < 4; ni++)
            #pragma unroll
            for (int v = 0; v < 4; v++) o[ni][v] = 0.f;

        #pragma unroll
        for (int ki = 0; ki < 8; ki++) {
            const float* ap = Ps + g * P_ST + ki * 8 + c;
            unsigned a0 = __float_as_uint(ap[0]);
            unsigned a1 = __float_as_uint(ap[8 * P_ST]);
            unsigned a2 = __float_as_uint(ap[4]);
            unsigned a3 = __float_as_uint(ap[8 * P_ST + 4]);
            #pragma unroll
            for (int ni = 0; ni < 4; ni++) {
                const float* bp = Vsm + (ki * 8 + c) * V_ST + ni * 8 + g;
                mma_tf32(o[ni], a0, a1, a2, a3,
                         __float_as_uint(bp[0]), __float_as_uint(bp[4 * V_ST]));
            }
        }

        // ---- store O (tf32-rounded for GEMM2) ----
        int r0 = mi * 16 + g, r1 = r0 + 8;
        #pragma unroll
        for (int ni = 0; ni < 4; ni++) {
            int col = ni * 8 + c * 2;
            float2 v0 = make_float2(rnd(o[ni][0]), rnd(o[ni][1]));
            float2 v1 = make_float2(rnd(o[ni][2]), rnd(o[ni][3]));
            *(float2*)(obh + (size_t)r0 * C_IN + col) = v0;
            *(float2*)(obh + (size_t)r1 * C_IN + col) = v1;
        }
    }
}

extern "C" void kernel_launch(void* const* d_in, const int* in_sizes, int n_in,
                              void* d_out, int out_size)
{
    const float* x      = (const float*)d_in[0];
    const float* w_qkv  = (const float*)d_in[1];
    const float* b_qkv  = (const float*)d_in[2];
    const float* w_proj = (const float*)d_in[3];
    const float* b_proj = (const float*)d_in[4];
    float* out = (float*)d_out;

    float* d_xc; cudaGetSymbolAddress((void**)&d_xc, g_xc);
    float* d_wq; cudaGetSymbolAddress((void**)&d_wq, g_wq);
    float* d_wp; cudaGetSymbolAddress((void**)&d_wp, g_wp);

    cudaFuncSetAttribute(gemm_tc<NQKV, true>,
                         cudaFuncAttributeMaxDynamicSharedMemorySize, SMEM_DYN);
    cudaFuncSetAttribute(gemm_tc<C_IN, false>,
                         cudaFuncAttributeMaxDynamicSharedMemorySize, SMEM_DYN);
    cudaFuncSetAttribute(attn_mma,
                         cudaFuncAttributeMaxDynamicSharedMemorySize, ATT_SMEM);

    // Stage 0: pre-round operands to tf32
    cvt_tf32_kernel<<<2048, 256>>>(x, d_xc, NX / 4);
    cvt_tf32_kernel<<<256, 256>>>(w_qkv, d_wq, (C_IN * NQKV) / 4);
    cvt_tf32_kernel<<<128, 256>>>(w_proj, d_wp, (C_IN * C_IN) / 4);

    // Stage 1: gathered QKV GEMM  (65536 x 1152 x 384)
    gemm_tc<NQKV, true><<<dim3(9, 512), 256, SMEM_DYN>>>(b_qkv, out);

    // Stage 2: window attention via tensor cores (1 warp per window-head)
    attn_mma<<<3072, 128, ATT_SMEM>>>();

    // Stage 3: proj GEMM with scatter (65536 x 384 x 384)
    gemm_tc<C_IN, false><<<dim3(3, 512), 256, SMEM_DYN>>>(b_proj, out);
}

// round 13
// speedup vs baseline: 2.3378x; 1.3517x over previous
#include <cuda_runtime.h>
#include <cuda_fp16.h>
#include <cstring>

typedef unsigned long long u64;

// Problem constants
#define C_IN   384
#define NQKV   1152
#define MROWS  65536        // 1024 windows * 64 tokens
#define SHIFT_ 4
#define NX     (16*64*64*384)   // 25,165,824

// Scratch (device globals; no allocation in kernel_launch)
__device__ float  g_qkv[(size_t)MROWS * NQKV];   // 302 MB fp32 qkv
__device__ __half g_att[(size_t)MROWS * C_IN];   // 50 MB attention out (half)
__device__ __half g_xc[(size_t)NX];              // 50 MB half x
__device__ __half g_wq[(size_t)NQKV * C_IN];     // w_qkv^T  [N][K] half
__device__ __half g_wp[(size_t)C_IN * C_IN];     // w_proj^T [N][K] half

__device__ __forceinline__ int pix_base(int m) {
    int w  = m >> 6;
    int t  = m & 63;
    int b  = w >> 6;
    int wh = (w >> 3) & 7;
    int ww = w & 7;
    int i  = t >> 3;
    int j  = t & 7;
    int r  = (wh * 8 + i + SHIFT_) & 63;
    int c  = (ww * 8 + j + SHIFT_) & 63;
    return ((b * 64 + r) * 64 + c) * C_IN;
}

__device__ __forceinline__ unsigned f2tf32(float f) {
    unsigned r;
    asm("cvt.rna.tf32.f32 %0, %1;" : "=r"(r) : "f"(f));
    return r;
}
__device__ __forceinline__ float rnd(float f) {
    return __uint_as_float(f2tf32(f));
}

__device__ __forceinline__ unsigned h2_bits(half2 h) {
    unsigned u;
    memcpy(&u, &h, 4);
    return u;
}

__device__ __forceinline__ void cp_async16(unsigned dst_smem, const void* src) {
    asm volatile("cp.async.cg.shared.global [%0], [%1], 16;"
                 :: "r"(dst_smem), "l"(src));
}

// fp16 MMA m16n8k16, fp32 accumulate
__device__ __forceinline__ void mma_f16(float* d, unsigned a0, unsigned a1,
                                        unsigned a2, unsigned a3,
                                        unsigned b0, unsigned b1) {
    asm volatile(
        "mma.sync.aligned.m16n8k16.row.col.f32.f16.f16.f32 "
        "{%0,%1,%2,%3}, {%4,%5,%6,%7}, {%8,%9}, {%0,%1,%2,%3};"
        : "+f"(d[0]), "+f"(d[1]), "+f"(d[2]), "+f"(d[3])
        : "r"(a0), "r"(a1), "r"(a2), "r"(a3), "r"(b0), "r"(b1));
}

// tf32 MMA m16n8k8 (attention)
__device__ __forceinline__ void mma_tf32(float* d, unsigned a0, unsigned a1,
                                         unsigned a2, unsigned a3,
                                         unsigned b0, unsigned b1) {
    asm volatile(
        "mma.sync.aligned.m16n8k8.row.col.f32.tf32.tf32.f32 "
        "{%0,%1,%2,%3}, {%4,%5,%6,%7}, {%8,%9}, {%0,%1,%2,%3};"
        : "+f"(d[0]), "+f"(d[1]), "+f"(d[2]), "+f"(d[3])
        : "r"(a0), "r"(a1), "r"(a2), "r"(a3), "r"(b0), "r"(b1));
}

// ---- prep: fp32 -> half elementwise (8 elems/thread-iter) ----
__global__ void cvt_half_kernel(const float* __restrict__ src,
                                __half* __restrict__ dst, int n8)
{
    int i = blockIdx.x * blockDim.x + threadIdx.x;
    int stride = gridDim.x * blockDim.x;
    for (; i < n8; i += stride) {
        float4 a = ((const float4*)src)[2 * i];
        float4 b = ((const float4*)src)[2 * i + 1];
        uint4 o;
        o.x = h2_bits(__floats2half2_rn(a.x, a.y));
        o.y = h2_bits(__floats2half2_rn(a.z, a.w));
        o.z = h2_bits(__floats2half2_rn(b.x, b.y));
        o.w = h2_bits(__floats2half2_rn(b.z, b.w));
        ((uint4*)dst)[i] = o;
    }
}

// ---- prep: transpose + cvt: src fp32 [K=384][N] -> dst half [N][384] ----
__global__ void transpose_half_kernel(const float* __restrict__ src,
                                      __half* __restrict__ dst, int total)
{
    int i = blockIdx.x * blockDim.x + threadIdx.x;
    int stride = gridDim.x * blockDim.x;
    int N = total / C_IN;
    for (; i < total; i += stride) {
        int n = i / C_IN, k = i - n * C_IN;
        dst[i] = __float2half(src[(size_t)k * N + n]);
    }
}

// ---- fp16 GEMM: 128x128 tile, K-chunk 64 halfs (4 k16 steps), 2-stage ----
// A smem [128][AST] halfs (k contig), B smem [128][BST] halfs (W^T: n rows, k contig)
// word-stride = AST/2 = 36 == 4 (mod 32) -> fragment banks (4g+c) all distinct
#define KCH  64
#define AST  72
#define BST  72
#define ABUF (128*AST)   // halfs
#define BBUF (128*BST)   // halfs
#define SMEM_DYN ((2*ABUF + 2*BBUF) * 2)   // 73728 bytes

template<int N, bool STAGE1>
__global__ __launch_bounds__(256, 2) void gemm_tc(const float* __restrict__ bias,
                                                  float* __restrict__ Y)
{
    extern __shared__ __half hsm[];
    __half* Asm = hsm;                 // 2 * ABUF
    __half* Bsm = hsm + 2 * ABUF;      // 2 * BBUF
    __shared__ int rowBase[128];
    __shared__ int outBase[128];

    const int tid = threadIdx.x;
    const int m0  = blockIdx.y * 128;
    const int n0  = blockIdx.x * 128;

    if (tid < 128) {
        int m = m0 + tid;
        rowBase[tid] = STAGE1 ? pix_base(m) : m * C_IN;
        if (!STAGE1) outBase[tid] = pix_base(m);
    }
    __syncthreads();

    const __half* Asrc = STAGE1 ? g_xc : g_att;
    const __half* Wt   = STAGE1 ? g_wq : g_wp;   // [N][384]

    const int warp = tid >> 5, lane = tid & 31;
    const int wm = warp >> 2;   // 0..1
    const int wn = warp & 3;    // 0..3
    const int g = lane >> 2, c = lane & 3;

    // staging: idx = tid + it*256 (0..1023): row = idx>>3, col8 = (idx&7)*8
    const int sRow = tid >> 3;
    const int sCol = (tid & 7) << 3;

    unsigned aDst0 = (unsigned)__cvta_generic_to_shared(Asm);
    unsigned bDst0 = (unsigned)__cvta_generic_to_shared(Bsm);

    float acc[4][4][4];
    #pragma unroll
    for (int mi = 0; mi < 4; mi++)
        #pragma unroll
        for (int ni = 0; ni < 4; ni++)
            #pragma unroll
            for (int v = 0; v < 4; v++) acc[mi][ni][v] = 0.f;

    const int NIT = C_IN / KCH;   // 6

    auto stage = [&](int chunk, int buf) {
        int k0 = chunk * KCH;
        #pragma unroll
        for (int it = 0; it < 4; it++) {
            int r = sRow + it * 32;
            cp_async16(aDst0 + (unsigned)((buf * ABUF + r * AST + sCol) * 2),
                       Asrc + rowBase[r] + k0 + sCol);
        }
        #pragma unroll
        for (int it = 0; it < 4; it++) {
            int r = sRow + it * 32;
            cp_async16(bDst0 + (unsigned)((buf * BBUF + r * BST + sCol) * 2),
                       Wt + (size_t)(n0 + r) * C_IN + k0 + sCol);
        }
        asm volatile("cp.async.commit_group;");
    };

    stage(0, 0);

    for (int itc = 0; itc < NIT; itc++) {
        asm volatile("cp.async.wait_group 0;");
        __syncthreads();
        if (itc + 1 < NIT) stage(itc + 1, (itc + 1) & 1);

        const __half* Ab = Asm + (itc & 1) * ABUF;
        const __half* Bb = Bsm + (itc & 1) * BBUF;

        #pragma unroll
        for (int ki = 0; ki < 4; ki++) {   // k16 steps
            unsigned af[4][4], bf[4][2];
            #pragma unroll
            for (int mi = 0; mi < 4; mi++) {
                const __half* ap = Ab + (wm * 64 + mi * 16 + g) * AST
                                      + ki * 16 + 2 * c;
                af[mi][0] = *(const unsigned*)(ap);
                af[mi][1] = *(const unsigned*)(ap + 8 * AST);
                af[mi][2] = *(const unsigned*)(ap + 8);
                af[mi][3] = *(const unsigned*)(ap + 8 * AST + 8);
            }
            #pragma unroll
            for (int ni = 0; ni < 4; ni++) {
                const __half* bp = Bb + (wn * 32 + ni * 8 + g) * BST
                                      + ki * 16 + 2 * c;
                bf[ni][0] = *(const unsigned*)(bp);
                bf[ni][1] = *(const unsigned*)(bp + 8);
            }
            #pragma unroll
            for (int mi = 0; mi < 4; mi++)
                #pragma unroll
                for (int ni = 0; ni < 4; ni++)
                    mma_f16(acc[mi][ni], af[mi][0], af[mi][1], af[mi][2],
                            af[mi][3], bf[ni][0], bf[ni][1]);
        }
        __syncthreads();
    }

    float* Ydst = STAGE1 ? g_qkv : Y;
    #pragma unroll
    for (int mi = 0; mi < 4; mi++) {
        int mrow = (wm * 4 + mi) * 16 + g;
        #pragma unroll
        for (int half_ = 0; half_ < 2; half_++) {
            int ml = mrow + half_ * 8;
            size_t ob = STAGE1 ? (size_t)(m0 + ml) * N : (size_t)outBase[ml];
            #pragma unroll
            for (int ni = 0; ni < 4; ni++) {
                int n = n0 + (wn * 4 + ni) * 8 + c * 2;
                float2 b2 = *(const float2*)(bias + n);
                float2 val;
                val.x = acc[mi][ni][half_ * 2 + 0] + b2.x;
                val.y = acc[mi][ni][half_ * 2 + 1] + b2.y;
                *(float2*)(Ydst + ob + n) = val;
            }
        }
    }
}

// ---- MMA attention: one warp per (window, head), 4 warps per block ----
#define KT_ST 72
#define V_ST  40
#define P_ST  68
#define WSL   (32*KT_ST + 64*V_ST + 16*P_ST)
#define ATT_SMEM (4 * WSL * 4)

__global__ __launch_bounds__(128) void attn_mma()
{
    extern __shared__ float sm[];
    const int warp = threadIdx.x >> 5, lane = threadIdx.x & 31;
    const int id = blockIdx.x * 4 + warp;
    const int w = id / 12, h = id - w * 12;

    float* Ksm = sm + warp * WSL;
    float* Vsm = Ksm + 32 * KT_ST;
    float* Ps  = Vsm + 64 * V_ST;

    const float* base = g_qkv + (size_t)w * 64 * NQKV;
    const int qo = h * 32, ko = 384 + h * 32, vo = 768 + h * 32;

    for (int e = lane; e < 512; e += 32) {
        int tok = e >> 3, d4 = (e & 7) << 2;
        float4 kv = *(const float4*)(base + tok * NQKV + ko + d4);
        Ksm[(d4 + 0) * KT_ST + tok] = rnd(kv.x);
        Ksm[(d4 + 1) * KT_ST + tok] = rnd(kv.y);
        Ksm[(d4 + 2) * KT_ST + tok] = rnd(kv.z);
        Ksm[(d4 + 3) * KT_ST + tok] = rnd(kv.w);
        float4 vv = *(const float4*)(base + tok * NQKV + vo + d4);
        vv.x = rnd(vv.x); vv.y = rnd(vv.y); vv.z = rnd(vv.z); vv.w = rnd(vv.w);
        *(float4*)&Vsm[tok * V_ST + d4] = vv;
    }
    __syncwarp();

    const int g = lane >> 2, c = lane & 3;
    const float scale = 0.17677669529663687f;
    __half* obh = g_att + (size_t)w * 64 * C_IN + h * 32;

    for (int mi = 0; mi < 4; mi++) {
        float s[8][4];
        #pragma unroll
        for (int ni = 0; ni < 8; ni++)
            #pragma unroll
            for (int v = 0; v < 4; v++) s[ni][v] = 0.f;

        #pragma unroll
        for (int ki = 0; ki < 4; ki++) {
            const float* qp = base + (mi * 16 + g) * NQKV + qo + ki * 8 + c;
            unsigned a0 = f2tf32(qp[0]);
            unsigned a1 = f2tf32(qp[8 * NQKV]);
            unsigned a2 = f2tf32(qp[4]);
            unsigned a3 = f2tf32(qp[8 * NQKV + 4]);
            #pragma unroll
            for (int ni = 0; ni < 8; ni++) {
                const float* bp = Ksm + (ki * 8 + c) * KT_ST + ni * 8 + g;
                mma_tf32(s[ni], a0, a1, a2, a3,
                         __float_as_uint(bp[0]), __float_as_uint(bp[4 * KT_ST]));
            }
        }

        float mA = -1e30f, mB = -1e30f;
        #pragma unroll
        for (int ni = 0; ni < 8; ni++) {
            mA = fmaxf(mA, fmaxf(s[ni][0], s[ni][1]));
            mB = fmaxf(mB, fmaxf(s[ni][2], s[ni][3]));
        }
        mA = fmaxf(mA, __shfl_xor_sync(0xffffffff, mA, 1));
        mA = fmaxf(mA, __shfl_xor_sync(0xffffffff, mA, 2));
        mB = fmaxf(mB, __shfl_xor_sync(0xffffffff, mB, 1));
        mB = fmaxf(mB, __shfl_xor_sync(0xffffffff, mB, 2));

        float sumA = 0.f, sumB = 0.f;
        #pragma unroll
        for (int ni = 0; ni < 8; ni++) {
            s[ni][0] = __expf((s[ni][0] - mA) * scale);
            s[ni][1] = __expf((s[ni][1] - mA) * scale);
            s[ni][2] = __expf((s[ni][2] - mB) * scale);
            s[ni][3] = __expf((s[ni][3] - mB) * scale);
            sumA += s[ni][0] + s[ni][1];
            sumB += s[ni][2] + s[ni][3];
        }
        sumA += __shfl_xor_sync(0xffffffff, sumA, 1);
        sumA += __shfl_xor_sync(0xffffffff, sumA, 2);
        sumB += __shfl_xor_sync(0xffffffff, sumB, 1);
        sumB += __shfl_xor_sync(0xffffffff, sumB, 2);
        float invA = 1.f / sumA, invB = 1.f / sumB;

        __syncwarp();
        #pragma unroll
        for (int ni = 0; ni < 8; ni++) {
            int col = ni * 8 + c * 2;
            Ps[g * P_ST + col]           = rnd(s[ni][0] * invA);
            Ps[g * P_ST + col + 1]       = rnd(s[ni][1] * invA);
            Ps[(g + 8) * P_ST + col]     = rnd(s[ni][2] * invB);
            Ps[(g + 8) * P_ST + col + 1] = rnd(s[ni][3] * invB);
        }
        __syncwarp();

        float o[4][4];
        #pragma unroll
        for (int ni = 0; ni < 4; ni++)
            #pragma unroll
            for (int v = 0; v < 4; v++) o[ni][v] = 0.f;

        #pragma unroll
        for (int ki = 0; ki < 8; ki++) {
            const float* ap = Ps + g * P_ST + ki * 8 + c;
            unsigned a0 = __float_as_uint(ap[0]);
            unsigned a1 = __float_as_uint(ap[8 * P_ST]);
            unsigned a2 = __float_as_uint(ap[4]);
            unsigned a3 = __float_as_uint(ap[8 * P_ST + 4]);
            #pragma unroll
            for (int ni = 0; ni < 4; ni++) {
                const float* bp = Vsm + (ki * 8 + c) * V_ST + ni * 8 + g;
                mma_tf32(o[ni], a0, a1, a2, a3,
                         __float_as_uint(bp[0]), __float_as_uint(bp[4 * V_ST]));
            }
        }

        int r0 = mi * 16 + g, r1 = r0 + 8;
        #pragma unroll
        for (int ni = 0; ni < 4; ni++) {
            int col = ni * 8 + c * 2;
            *(half2*)(obh + (size_t)r0 * C_IN + col) =
                __floats2half2_rn(o[ni][0], o[ni][1]);
            *(half2*)(obh + (size_t)r1 * C_IN + col) =
                __floats2half2_rn(o[ni][2], o[ni][3]);
        }
    }
}

extern "C" void kernel_launch(void* const* d_in, const int* in_sizes, int n_in,
                              void* d_out, int out_size)
{
    const float* x      = (const float*)d_in[0];
    const float* w_qkv  = (const float*)d_in[1];
    const float* b_qkv  = (const float*)d_in[2];
    const float* w_proj = (const float*)d_in[3];
    const float* b_proj = (const float*)d_in[4];
    float* out = (float*)d_out;

    __half* d_xc; cudaGetSymbolAddress((void**)&d_xc, g_xc);
    __half* d_wq; cudaGetSymbolAddress((void**)&d_wq, g_wq);
    __half* d_wp; cudaGetSymbolAddress((void**)&d_wp, g_wp);

    cudaFuncSetAttribute(gemm_tc<NQKV, true>,
                         cudaFuncAttributeMaxDynamicSharedMemorySize, SMEM_DYN);
    cudaFuncSetAttribute(gemm_tc<C_IN, false>,
                         cudaFuncAttributeMaxDynamicSharedMemorySize, SMEM_DYN);
    cudaFuncSetAttribute(attn_mma,
                         cudaFuncAttributeMaxDynamicSharedMemorySize, ATT_SMEM);

    // Stage 0: convert x -> half; transpose+convert weights -> [N][K] half
    cvt_half_kernel<<<2048, 256>>>(x, d_xc, NX / 8);
    transpose_half_kernel<<<1728, 256>>>(w_qkv, d_wq, NQKV * C_IN);
    transpose_half_kernel<<<576, 256>>>(w_proj, d_wp, C_IN * C_IN);

    // Stage 1: gathered QKV GEMM (65536 x 1152 x 384), fp16 tensor cores
    gemm_tc<NQKV, true><<<dim3(9, 512), 256, SMEM_DYN>>>(b_qkv, out);

    // Stage 2: window attention via tf32 tensor cores
    attn_mma<<<3072, 128, ATT_SMEM>>>();

    // Stage 3: proj GEMM with scatter (65536 x 384 x 384), fp16 tensor cores
    gemm_tc<C_IN, false><<<dim3(3, 512), 256, SMEM_DYN>>>(b_proj, out);
}

// round 14
// speedup vs baseline: 2.7809x; 1.1895x over previous
#include <cuda_runtime.h>
#include <cuda_fp16.h>
#include <cstring>

typedef unsigned long long u64;

// Problem constants
#define C_IN   384
#define NQKV   1152
#define MROWS  65536        // 1024 windows * 64 tokens
#define SHIFT_ 4
#define NX     (16*64*64*384)   // 25,165,824

// Scratch (device globals; no allocation in kernel_launch)
__device__ __half g_qkv[(size_t)MROWS * NQKV];   // 151 MB half qkv
__device__ __half g_att[(size_t)MROWS * C_IN];   // 50 MB attention out (half)
__device__ __half g_xc[(size_t)NX];              // 50 MB half x
__device__ __half g_wq[(size_t)NQKV * C_IN];     // w_qkv^T  [N][K] half
__device__ __half g_wp[(size_t)C_IN * C_IN];     // w_proj^T [N][K] half

__device__ __forceinline__ int pix_base(int m) {
    int w  = m >> 6;
    int t  = m & 63;
    int b  = w >> 6;
    int wh = (w >> 3) & 7;
    int ww = w & 7;
    int i  = t >> 3;
    int j  = t & 7;
    int r  = (wh * 8 + i + SHIFT_) & 63;
    int c  = (ww * 8 + j + SHIFT_) & 63;
    return ((b * 64 + r) * 64 + c) * C_IN;
}

__device__ __forceinline__ unsigned h2_bits(half2 h) {
    unsigned u;
    memcpy(&u, &h, 4);
    return u;
}

__device__ __forceinline__ void cp_async16(unsigned dst_smem, const void* src) {
    asm volatile("cp.async.cg.shared.global [%0], [%1], 16;"
                 :: "r"(dst_smem), "l"(src));
}

// fp16 MMA m16n8k16, fp32 accumulate
__device__ __forceinline__ void mma_f16(float* d, unsigned a0, unsigned a1,
                                        unsigned a2, unsigned a3,
                                        unsigned b0, unsigned b1) {
    asm volatile(
        "mma.sync.aligned.m16n8k16.row.col.f32.f16.f16.f32 "
        "{%0,%1,%2,%3}, {%4,%5,%6,%7}, {%8,%9}, {%0,%1,%2,%3};"
        : "+f"(d[0]), "+f"(d[1]), "+f"(d[2]), "+f"(d[3])
        : "r"(a0), "r"(a1), "r"(a2), "r"(a3), "r"(b0), "r"(b1));
}

// ---- prep: fp32 -> half elementwise (8 elems/thread-iter) ----
__global__ void cvt_half_kernel(const float* __restrict__ src,
                                __half* __restrict__ dst, int n8)
{
    int i = blockIdx.x * blockDim.x + threadIdx.x;
    int stride = gridDim.x * blockDim.x;
    for (; i < n8; i += stride) {
        float4 a = ((const float4*)src)[2 * i];
        float4 b = ((const float4*)src)[2 * i + 1];
        uint4 o;
        o.x = h2_bits(__floats2half2_rn(a.x, a.y));
        o.y = h2_bits(__floats2half2_rn(a.z, a.w));
        o.z = h2_bits(__floats2half2_rn(b.x, b.y));
        o.w = h2_bits(__floats2half2_rn(b.z, b.w));
        ((uint4*)dst)[i] = o;
    }
}

// ---- prep: transpose + cvt: src fp32 [K=384][N] -> dst half [N][384] ----
__global__ void transpose_half_kernel(const float* __restrict__ src,
                                      __half* __restrict__ dst, int total)
{
    int i = blockIdx.x * blockDim.x + threadIdx.x;
    int stride = gridDim.x * blockDim.x;
    int N = total / C_IN;
    for (; i < total; i += stride) {
        int n = i / C_IN, k = i - n * C_IN;
        dst[i] = __float2half(src[(size_t)k * N + n]);
    }
}

// ---- fp16 GEMM: 128x128 tile, K-chunk 64 halfs (4 k16 steps), 2-stage ----
#define KCH  64
#define AST  72
#define BST  72
#define ABUF (128*AST)   // halfs
#define BBUF (128*BST)   // halfs
#define SMEM_DYN ((2*ABUF + 2*BBUF) * 2)   // 73728 bytes

template<int N, bool STAGE1>
__global__ __launch_bounds__(256, 2) void gemm_tc(const float* __restrict__ bias,
                                                  float* __restrict__ Y)
{
    extern __shared__ __half hsm[];
    __half* Asm = hsm;
    __half* Bsm = hsm + 2 * ABUF;
    __shared__ int rowBase[128];
    __shared__ int outBase[128];

    const int tid = threadIdx.x;
    const int m0  = blockIdx.y * 128;
    const int n0  = blockIdx.x * 128;

    if (tid < 128) {
        int m = m0 + tid;
        rowBase[tid] = STAGE1 ? pix_base(m) : m * C_IN;
        if (!STAGE1) outBase[tid] = pix_base(m);
    }
    __syncthreads();

    const __half* Asrc = STAGE1 ? g_xc : g_att;
    const __half* Wt   = STAGE1 ? g_wq : g_wp;

    const int warp = tid >> 5, lane = tid & 31;
    const int wm = warp >> 2;
    const int wn = warp & 3;
    const int g = lane >> 2, c = lane & 3;

    const int sRow = tid >> 3;
    const int sCol = (tid & 7) << 3;

    unsigned aDst0 = (unsigned)__cvta_generic_to_shared(Asm);
    unsigned bDst0 = (unsigned)__cvta_generic_to_shared(Bsm);

    float acc[4][4][4];
    #pragma unroll
    for (int mi = 0; mi < 4; mi++)
        #pragma unroll
        for (int ni = 0; ni < 4; ni++)
            #pragma unroll
            for (int v = 0; v < 4; v++) acc[mi][ni][v] = 0.f;

    const int NIT = C_IN / KCH;   // 6

    auto stage = [&](int chunk, int buf) {
        int k0 = chunk * KCH;
        #pragma unroll
        for (int it = 0; it < 4; it++) {
            int r = sRow + it * 32;
            cp_async16(aDst0 + (unsigned)((buf * ABUF + r * AST + sCol) * 2),
                       Asrc + rowBase[r] + k0 + sCol);
        }
        #pragma unroll
        for (int it = 0; it < 4; it++) {
            int r = sRow + it * 32;
            cp_async16(bDst0 + (unsigned)((buf * BBUF + r * BST + sCol) * 2),
                       Wt + (size_t)(n0 + r) * C_IN + k0 + sCol);
        }
        asm volatile("cp.async.commit_group;");
    };

    stage(0, 0);

    for (int itc = 0; itc < NIT; itc++) {
        asm volatile("cp.async.wait_group 0;");
        __syncthreads();
        if (itc + 1 < NIT) stage(itc + 1, (itc + 1) & 1);

        const __half* Ab = Asm + (itc & 1) * ABUF;
        const __half* Bb = Bsm + (itc & 1) * BBUF;

        #pragma unroll
        for (int ki = 0; ki < 4; ki++) {
            unsigned af[4][4], bf[4][2];
            #pragma unroll
            for (int mi = 0; mi < 4; mi++) {
                const __half* ap = Ab + (wm * 64 + mi * 16 + g) * AST
                                      + ki * 16 + 2 * c;
                af[mi][0] = *(const unsigned*)(ap);
                af[mi][1] = *(const unsigned*)(ap + 8 * AST);
                af[mi][2] = *(const unsigned*)(ap + 8);
                af[mi][3] = *(const unsigned*)(ap + 8 * AST + 8);
            }
            #pragma unroll
            for (int ni = 0; ni < 4; ni++) {
                const __half* bp = Bb + (wn * 32 + ni * 8 + g) * BST
                                      + ki * 16 + 2 * c;
                bf[ni][0] = *(const unsigned*)(bp);
                bf[ni][1] = *(const unsigned*)(bp + 8);
            }
            #pragma unroll
            for (int mi = 0; mi < 4; mi++)
                #pragma unroll
                for (int ni = 0; ni < 4; ni++)
                    mma_f16(acc[mi][ni], af[mi][0], af[mi][1], af[mi][2],
                            af[mi][3], bf[ni][0], bf[ni][1]);
        }
        __syncthreads();
    }

    #pragma unroll
    for (int mi = 0; mi < 4; mi++) {
        int mrow = (wm * 4 + mi) * 16 + g;
        #pragma unroll
        for (int half_ = 0; half_ < 2; half_++) {
            int ml = mrow + half_ * 8;
            #pragma unroll
            for (int ni = 0; ni < 4; ni++) {
                int n = n0 + (wn * 4 + ni) * 8 + c * 2;
                float2 b2 = *(const float2*)(bias + n);
                float vx = acc[mi][ni][half_ * 2 + 0] + b2.x;
                float vy = acc[mi][ni][half_ * 2 + 1] + b2.y;
                if (STAGE1) {
                    size_t ob = (size_t)(m0 + ml) * N;
                    *(half2*)(g_qkv + ob + n) = __floats2half2_rn(vx, vy);
                } else {
                    size_t ob = (size_t)outBase[ml];
                    *(float2*)(Y + ob + n) = make_float2(vx, vy);
                }
            }
        }
    }
}

// ---- fp16 MMA attention: one warp per (window, head), 4 warps/block ----
// Warp-private half tiles:
//   Qs[64][40], Ks[64][40]  (word-stride 20 -> banks {0,20,8,28,16,4,24,12}+c, distinct)
//   Vt[32][72] (V^T), Ps[16][72]  (word-stride 36 == 4 mod 32 -> (4g+c), distinct)
#define Q_ST  40
#define K_ST  40
#define VT_ST 72
#define P_ST  72
#define WSLH  (64*Q_ST + 64*K_ST + 32*VT_ST + 16*P_ST)   // 8576 halfs
#define ATT_SMEM (4 * WSLH * 2)                          // 68608 bytes

__global__ __launch_bounds__(128) void attn_mma()
{
    extern __shared__ __half hsmem[];
    const int warp = threadIdx.x >> 5, lane = threadIdx.x & 31;
    const int id = blockIdx.x * 4 + warp;
    const int w = id / 12, h = id - w * 12;

    __half* Qs = hsmem + warp * WSLH;
    __half* Ks = Qs + 64 * Q_ST;
    __half* Vt = Ks + 64 * K_ST;
    __half* Ps = Vt + 32 * VT_ST;

    const __half* base = g_qkv + (size_t)w * 64 * NQKV;
    const int qo = h * 32, ko = 384 + h * 32, vo = 768 + h * 32;

    // stage Q and K (vectorized, natural layout)
    for (int e = lane; e < 256; e += 32) {
        int tok = e >> 2, d8 = (e & 3) << 3;
        *(uint4*)(Qs + tok * Q_ST + d8) = *(const uint4*)(base + tok * NQKV + qo + d8);
        *(uint4*)(Ks + tok * K_ST + d8) = *(const uint4*)(base + tok * NQKV + ko + d8);
    }
    // stage V transposed: Vt[d][tok]
    for (int e = lane; e < 2048; e += 32) {
        int tok = e >> 5, d = e & 31;
        Vt[d * VT_ST + tok] = base[tok * NQKV + vo + d];
    }
    __syncwarp();

    const int g = lane >> 2, c = lane & 3;
    const float scale = 0.17677669529663687f;   // 1/sqrt(32)
    __half* obh = g_att + (size_t)w * 64 * C_IN + h * 32;

    for (int mi = 0; mi < 4; mi++) {
        // ---- S = Q @ K^T  (m16 x n64, k32: 2 k16 steps) ----
        float s[8][4];
        #pragma unroll
        for (int ni = 0; ni < 8; ni++)
            #pragma unroll
            for (int v = 0; v < 4; v++) s[ni][v] = 0.f;

        #pragma unroll
        for (int ki = 0; ki < 2; ki++) {
            const __half* ap = Qs + (mi * 16 + g) * Q_ST + ki * 16 + 2 * c;
            unsigned a0 = *(const unsigned*)(ap);
            unsigned a1 = *(const unsigned*)(ap + 8 * Q_ST);
            unsigned a2 = *(const unsigned*)(ap + 8);
            unsigned a3 = *(const unsigned*)(ap + 8 * Q_ST + 8);
            #pragma unroll
            for (int ni = 0; ni < 8; ni++) {
                const __half* bp = Ks + (ni * 8 + g) * K_ST + ki * 16 + 2 * c;
                mma_f16(s[ni], a0, a1, a2, a3,
                        *(const unsigned*)(bp), *(const unsigned*)(bp + 8));
            }
        }

        // ---- softmax over the two rows this thread covers ----
        float mA = -1e30f, mB = -1e30f;
        #pragma unroll
        for (int ni = 0; ni < 8; ni++) {
            mA = fmaxf(mA, fmaxf(s[ni][0], s[ni][1]));
            mB = fmaxf(mB, fmaxf(s[ni][2], s[ni][3]));
        }
        mA = fmaxf(mA, __shfl_xor_sync(0xffffffff, mA, 1));
        mA = fmaxf(mA, __shfl_xor_sync(0xffffffff, mA, 2));
        mB = fmaxf(mB, __shfl_xor_sync(0xffffffff, mB, 1));
        mB = fmaxf(mB, __shfl_xor_sync(0xffffffff, mB, 2));

        float sumA = 0.f, sumB = 0.f;
        #pragma unroll
        for (int ni = 0; ni < 8; ni++) {
            s[ni][0] = __expf((s[ni][0] - mA) * scale);
            s[ni][1] = __expf((s[ni][1] - mA) * scale);
            s[ni][2] = __expf((s[ni][2] - mB) * scale);
            s[ni][3] = __expf((s[ni][3] - mB) * scale);
            sumA += s[ni][0] + s[ni][1];
            sumB += s[ni][2] + s[ni][3];
        }
        sumA += __shfl_xor_sync(0xffffffff, sumA, 1);
        sumA += __shfl_xor_sync(0xffffffff, sumA, 2);
        sumB += __shfl_xor_sync(0xffffffff, sumB, 1);
        sumB += __shfl_xor_sync(0xffffffff, sumB, 2);
        float invA = 1.f / sumA, invB = 1.f / sumB;

        // ---- normalized half P -> smem ----
        __syncwarp();
        #pragma unroll
        for (int ni = 0; ni < 8; ni++) {
            int col = ni * 8 + c * 2;
            *(half2*)(Ps + g * P_ST + col) =
                __floats2half2_rn(s[ni][0] * invA, s[ni][1] * invA);
            *(half2*)(Ps + (g + 8) * P_ST + col) =
                __floats2half2_rn(s[ni][2] * invB, s[ni][3] * invB);
        }
        __syncwarp();

        // ---- O = P @ V  (m16 x n32, k64: 4 k16 steps) ----
        float o[4][4];
        #pragma unroll
        for (int ni = 0; ni < 4; ni++)
            #pragma unroll
            for (int v = 0; v < 4; v++) o[ni][v] = 0.f;

        #pragma unroll
        for (int ki = 0; ki < 4; ki++) {
            const __half* ap = Ps + g * P_ST + ki * 16 + 2 * c;
            unsigned a0 = *(const unsigned*)(ap);
            unsigned a1 = *(const unsigned*)(ap + 8 * P_ST);
            unsigned a2 = *(const unsigned*)(ap + 8);
            unsigned a3 = *(const unsigned*)(ap + 8 * P_ST + 8);
            #pragma unroll
            for (int ni = 0; ni < 4; ni++) {
                const __half* bp = Vt + (ni * 8 + g) * VT_ST + ki * 16 + 2 * c;
                mma_f16(o[ni], a0, a1, a2, a3,
                        *(const unsigned*)(bp), *(const unsigned*)(bp + 8));
            }
        }

        // ---- store O (half, for GEMM2) ----
        int r0 = mi * 16 + g, r1 = r0 + 8;
        #pragma unroll
        for (int ni = 0; ni < 4; ni++) {
            int col = ni * 8 + c * 2;
            *(half2*)(obh + (size_t)r0 * C_IN + col) =
                __floats2half2_rn(o[ni][0], o[ni][1]);
            *(half2*)(obh + (size_t)r1 * C_IN + col) =
                __floats2half2_rn(o[ni][2], o[ni][3]);
        }
    }
}

extern "C" void kernel_launch(void* const* d_in, const int* in_sizes, int n_in,
                              void* d_out, int out_size)
{
    const float* x      = (const float*)d_in[0];
    const float* w_qkv  = (const float*)d_in[1];
    const float* b_qkv  = (const float*)d_in[2];
    const float* w_proj = (const float*)d_in[3];
    const float* b_proj = (const float*)d_in[4];
    float* out = (float*)d_out;

    __half* d_xc; cudaGetSymbolAddress((void**)&d_xc, g_xc);
    __half* d_wq; cudaGetSymbolAddress((void**)&d_wq, g_wq);
    __half* d_wp; cudaGetSymbolAddress((void**)&d_wp, g_wp);

    cudaFuncSetAttribute(gemm_tc<NQKV, true>,
                         cudaFuncAttributeMaxDynamicSharedMemorySize, SMEM_DYN);
    cudaFuncSetAttribute(gemm_tc<C_IN, false>,
                         cudaFuncAttributeMaxDynamicSharedMemorySize, SMEM_DYN);
    cudaFuncSetAttribute(attn_mma,
                         cudaFuncAttributeMaxDynamicSharedMemorySize, ATT_SMEM);

    // Stage 0: convert x -> half; transpose+convert weights -> [N][K] half
    cvt_half_kernel<<<2048, 256>>>(x, d_xc, NX / 8);
    transpose_half_kernel<<<1728, 256>>>(w_qkv, d_wq, NQKV * C_IN);
    transpose_half_kernel<<<576, 256>>>(w_proj, d_wp, C_IN * C_IN);

    // Stage 1: gathered QKV GEMM (65536 x 1152 x 384), fp16 tensor cores
    gemm_tc<NQKV, true><<<dim3(9, 512), 256, SMEM_DYN>>>(b_qkv, out);

    // Stage 2: window attention via fp16 tensor cores
    attn_mma<<<3072, 128, ATT_SMEM>>>();

    // Stage 3: proj GEMM with scatter (65536 x 384 x 384), fp16 tensor cores
    gemm_tc<C_IN, false><<<dim3(3, 512), 256, SMEM_DYN>>>(b_proj, out);
}

// round 16
// speedup vs baseline: 2.9051x; 1.0446x over previous
#include <cuda_runtime.h>
#include <cuda_fp16.h>
#include <cstring>

typedef unsigned long long u64;

// Problem constants
#define C_IN   384
#define NQKV   1152
#define MROWS  65536        // 1024 windows * 64 tokens
#define SHIFT_ 4
#define NX     (16*64*64*384)   // 25,165,824

// Scratch (device globals; no allocation in kernel_launch)
__device__ __half g_qkv[(size_t)MROWS * NQKV];   // 151 MB half qkv
__device__ __half g_att[(size_t)MROWS * C_IN];   // 50 MB attention out (half)
__device__ __half g_xc[(size_t)NX];              // 50 MB half x
__device__ __half g_wq[(size_t)NQKV * C_IN];     // w_qkv^T  [N][K] half
__device__ __half g_wp[(size_t)C_IN * C_IN];     // w_proj^T [N][K] half

__device__ __forceinline__ int pix_base(int m) {
    int w  = m >> 6;
    int t  = m & 63;
    int b  = w >> 6;
    int wh = (w >> 3) & 7;
    int ww = w & 7;
    int i  = t >> 3;
    int j  = t & 7;
    int r  = (wh * 8 + i + SHIFT_) & 63;
    int c  = (ww * 8 + j + SHIFT_) & 63;
    return ((b * 64 + r) * 64 + c) * C_IN;
}

__device__ __forceinline__ unsigned h2_bits(half2 h) {
    unsigned u;
    memcpy(&u, &h, 4);
    return u;
}

__device__ __forceinline__ void cp_async16(unsigned dst_smem, const void* src) {
    asm volatile("cp.async.cg.shared.global [%0], [%1], 16;"
                 :: "r"(dst_smem), "l"(src));
}

__device__ __forceinline__ unsigned smem_u32(const void* p) {
    unsigned a;
    asm("{ .reg .u64 t; cvta.to.shared.u64 t, %1; cvt.u32.u64 %0, t; }"
        : "=r"(a) : "l"(p));
    return a;
}

// ldmatrix x4 (non-transposed): 4 8x8 half matrices
__device__ __forceinline__ void ldsm_x4(unsigned& r0, unsigned& r1,
                                        unsigned& r2, unsigned& r3,
                                        unsigned addr) {
    asm volatile("ldmatrix.sync.aligned.m8n8.x4.shared.b16 {%0,%1,%2,%3}, [%4];"
                 : "=r"(r0), "=r"(r1), "=r"(r2), "=r"(r3) : "r"(addr));
}

// fp16 warp MMA m16n8k16, fp32 accumulate
__device__ __forceinline__ void mma_f16(float* d, unsigned a0, unsigned a1,
                                        unsigned a2, unsigned a3,
                                        unsigned b0, unsigned b1) {
    asm volatile(
        "mma.sync.aligned.m16n8k16.row.col.f32.f16.f16.f32 "
        "{%0,%1,%2,%3}, {%4,%5,%6,%7}, {%8,%9}, {%0,%1,%2,%3};"
        : "+f"(d[0]), "+f"(d[1]), "+f"(d[2]), "+f"(d[3])
        : "r"(a0), "r"(a1), "r"(a2), "r"(a3), "r"(b0), "r"(b1));
}

// ---- prep: fp32 -> half elementwise (8 elems/thread-iter) ----
__global__ void cvt_half_kernel(const float* __restrict__ src,
                                __half* __restrict__ dst, int n8)
{
    int i = blockIdx.x * blockDim.x + threadIdx.x;
    int stride = gridDim.x * blockDim.x;
    for (; i < n8; i += stride) {
        float4 a = ((const float4*)src)[2 * i];
        float4 b = ((const float4*)src)[2 * i + 1];
        uint4 o;
        o.x = h2_bits(__floats2half2_rn(a.x, a.y));
        o.y = h2_bits(__floats2half2_rn(a.z, a.w));
        o.z = h2_bits(__floats2half2_rn(b.x, b.y));
        o.w = h2_bits(__floats2half2_rn(b.z, b.w));
        ((uint4*)dst)[i] = o;
    }
}

// ---- prep: transpose + cvt: src fp32 [K=384][N] -> dst half [N][384] ----
__global__ void transpose_half_kernel(const float* __restrict__ src,
                                      __half* __restrict__ dst, int total)
{
    int i = blockIdx.x * blockDim.x + threadIdx.x;
    int stride = gridDim.x * blockDim.x;
    int N = total / C_IN;
    for (; i < total; i += stride) {
        int n = i / C_IN, k = i - n * C_IN;
        dst[i] = __float2half(src[(size_t)k * N + n]);
    }
}

// ---- fp16 GEMM: 128x128 tile, K-chunk 64 halfs (4 k16 steps), 2-stage ----
#define KCH  64
#define AST  72
#define BST  72
#define ABUF (128*AST)   // halfs
#define BBUF (128*BST)   // halfs
#define SMEM_DYN ((2*ABUF + 2*BBUF) * 2)   // 73728 bytes

template<int N, bool STAGE1>
__global__ __launch_bounds__(256, 2) void gemm_tc(const float* __restrict__ bias,
                                                  float* __restrict__ Y)
{
    extern __shared__ __half hsm[];
    __half* Asm = hsm;
    __half* Bsm = hsm + 2 * ABUF;
    __shared__ int rowBase[128];
    __shared__ int outBase[128];

    const int tid = threadIdx.x;
    const int m0  = blockIdx.y * 128;
    const int n0  = blockIdx.x * 128;

    if (tid < 128) {
        int m = m0 + tid;
        rowBase[tid] = STAGE1 ? pix_base(m) : m * C_IN;
        if (!STAGE1) outBase[tid] = pix_base(m);
    }
    __syncthreads();

    const __half* Asrc = STAGE1 ? g_xc : g_att;
    const __half* Wt   = STAGE1 ? g_wq : g_wp;

    const int warp = tid >> 5, lane = tid & 31;
    const int wm = warp >> 2;
    const int wn = warp & 3;
    const int g = lane >> 2, c = lane & 3;

    const int sRow = tid >> 3;
    const int sCol = (tid & 7) << 3;

    unsigned aSm = smem_u32(Asm);
    unsigned bSm = smem_u32(Bsm);

    // ldmatrix per-lane coordinates
    const int aRowL = lane & 15;                 // + wm*64 + mi*16
    const int aColL = (lane >> 4) << 3;          // + ki*16
    const int bRowL = ((lane >> 4) << 3) + (lane & 7);   // + wn*32 + nj*16
    const int bColL = ((lane >> 3) & 1) << 3;            // + ki*16

    float acc[4][4][4];
    #pragma unroll
    for (int mi = 0; mi < 4; mi++)
        #pragma unroll
        for (int ni = 0; ni < 4; ni++)
            #pragma unroll
            for (int v = 0; v < 4; v++) acc[mi][ni][v] = 0.f;

    const int NIT = C_IN / KCH;   // 6

    auto stage = [&](int chunk, int buf) {
        int k0 = chunk * KCH;
        #pragma unroll
        for (int it = 0; it < 4; it++) {
            int r = sRow + it * 32;
            cp_async16(aSm + (unsigned)((buf * ABUF + r * AST + sCol) * 2),
                       Asrc + rowBase[r] + k0 + sCol);
        }
        #pragma unroll
        for (int it = 0; it < 4; it++) {
            int r = sRow + it * 32;
            cp_async16(bSm + (unsigned)((buf * BBUF + r * BST + sCol) * 2),
                       Wt + (size_t)(n0 + r) * C_IN + k0 + sCol);
        }
        asm volatile("cp.async.commit_group;");
    };

    stage(0, 0);

    for (int itc = 0; itc < NIT; itc++) {
        asm volatile("cp.async.wait_group 0;");
        __syncthreads();
        if (itc + 1 < NIT) stage(itc + 1, (itc + 1) & 1);

        const unsigned aB = aSm + (unsigned)((itc & 1) * ABUF * 2);
        const unsigned bB = bSm + (unsigned)((itc & 1) * BBUF * 2);

        #pragma unroll
        for (int ki = 0; ki < 4; ki++) {
            unsigned af[4][4], bf[4][2];
            #pragma unroll
            for (int mi = 0; mi < 4; mi++) {
                int row = wm * 64 + mi * 16 + aRowL;
                int col = ki * 16 + aColL;
                ldsm_x4(af[mi][0], af[mi][1], af[mi][2], af[mi][3],
                        aB + (unsigned)((row * AST + col) * 2));
            }
            #pragma unroll
            for (int nj = 0; nj < 2; nj++) {
                int row = wn * 32 + nj * 16 + bRowL;
                int col = ki * 16 + bColL;
                ldsm_x4(bf[2*nj][0], bf[2*nj][1], bf[2*nj+1][0], bf[2*nj+1][1],
                        bB + (unsigned)((row * BST + col) * 2));
            }
            #pragma unroll
            for (int mi = 0; mi < 4; mi++)
                #pragma unroll
                for (int ni = 0; ni < 4; ni++)
                    mma_f16(acc[mi][ni], af[mi][0], af[mi][1], af[mi][2],
                            af[mi][3], bf[ni][0], bf[ni][1]);
        }
        __syncthreads();
    }

    #pragma unroll
    for (int mi = 0; mi < 4; mi++) {
        int mrow = (wm * 4 + mi) * 16 + g;
        #pragma unroll
        for (int half_ = 0; half_ < 2; half_++) {
            int ml = mrow + half_ * 8;
            #pragma unroll
            for (int ni = 0; ni < 4; ni++) {
                int n = n0 + (wn * 4 + ni) * 8 + c * 2;
                float2 b2 = *(const float2*)(bias + n);
                float vx = acc[mi][ni][half_ * 2 + 0] + b2.x;
                float vy = acc[mi][ni][half_ * 2 + 1] + b2.y;
                if (STAGE1) {
                    size_t ob = (size_t)(m0 + ml) * N;
                    *(half2*)(g_qkv + ob + n) = __floats2half2_rn(vx, vy);
                } else {
                    size_t ob = (size_t)outBase[ml];
                    *(float2*)(Y + ob + n) = make_float2(vx, vy);
                }
            }
        }
    }
}

// ---- fp16 MMA attention: one warp per (window, head), 4 warps/block ----
#define Q_ST  40
#define K_ST  40
#define VT_ST 72
#define P_ST  72
#define WSLH  (64*Q_ST + 64*K_ST + 32*VT_ST + 16*P_ST)   // 8576 halfs
#define ATT_SMEM (4 * WSLH * 2)                          // 68608 bytes

__global__ __launch_bounds__(128) void attn_mma()
{
    extern __shared__ __half hsmem[];
    const int warp = threadIdx.x >> 5, lane = threadIdx.x & 31;
    const int id = blockIdx.x * 4 + warp;
    const int w = id / 12, h = id - w * 12;

    __half* Qs = hsmem + warp * WSLH;
    __half* Ks = Qs + 64 * Q_ST;
    __half* Vt = Ks + 64 * K_ST;
    __half* Ps = Vt + 32 * VT_ST;

    unsigned qSm = smem_u32(Qs);
    unsigned kSm = smem_u32(Ks);
    unsigned vSm = smem_u32(Vt);
    unsigned pSm = smem_u32(Ps);

    const __half* base = g_qkv + (size_t)w * 64 * NQKV;
    const int qo = h * 32, ko = 384 + h * 32, vo = 768 + h * 32;

    for (int e = lane; e < 256; e += 32) {
        int tok = e >> 2, d8 = (e & 3) << 3;
        *(uint4*)(Qs + tok * Q_ST + d8) = *(const uint4*)(base + tok * NQKV + qo + d8);
        *(uint4*)(Ks + tok * K_ST + d8) = *(const uint4*)(base + tok * NQKV + ko + d8);
    }
    for (int e = lane; e < 2048; e += 32) {
        int tok = e >> 5, d = e & 31;
        Vt[d * VT_ST + tok] = base[tok * NQKV + vo + d];
    }
    __syncwarp();

    const int g = lane >> 2, c = lane & 3;
    const int aRowL = lane & 15;
    const int aColL = (lane >> 4) << 3;
    const int bRowL = ((lane >> 4) << 3) + (lane & 7);
    const int bColL = ((lane >> 3) & 1) << 3;
    const float scale = 0.17677669529663687f;   // 1/sqrt(32)
    __half* obh = g_att + (size_t)w * 64 * C_IN + h * 32;

    for (int mi = 0; mi < 4; mi++) {
        // ---- S = Q @ K^T  (m16 x n64, k32: 2 k16 steps) ----
        float s[8][4];
        #pragma unroll
        for (int ni = 0; ni < 8; ni++)
            #pragma unroll
            for (int v = 0; v < 4; v++) s[ni][v] = 0.f;

        #pragma unroll
        for (int ki = 0; ki < 2; ki++) {
            unsigned a0, a1, a2, a3;
            {
                int row = mi * 16 + aRowL;
                int col = ki * 16 + aColL;
                ldsm_x4(a0, a1, a2, a3, qSm + (unsigned)((row * Q_ST + col) * 2));
            }
            #pragma unroll
            for (int nj = 0; nj < 4; nj++) {
                unsigned b0, b1, b2, b3;
                int row = nj * 16 + bRowL;
                int col = ki * 16 + bColL;
                ldsm_x4(b0, b1, b2, b3, kSm + (unsigned)((row * K_ST + col) * 2));
                mma_f16(s[2*nj],     a0, a1, a2, a3, b0, b1);
                mma_f16(s[2*nj + 1], a0, a1, a2, a3, b2, b3);
            }
        }

        // ---- softmax over the two rows this thread covers ----
        float mA = -1e30f, mB = -1e30f;
        #pragma unroll
        for (int ni = 0; ni < 8; ni++) {
            mA = fmaxf(mA, fmaxf(s[ni][0], s[ni][1]));
            mB = fmaxf(mB, fmaxf(s[ni][2], s[ni][3]));
        }
        mA = fmaxf(mA, __shfl_xor_sync(0xffffffff, mA, 1));
        mA = fmaxf(mA, __shfl_xor_sync(0xffffffff, mA, 2));
        mB = fmaxf(mB, __shfl_xor_sync(0xffffffff, mB, 1));
        mB = fmaxf(mB, __shfl_xor_sync(0xffffffff, mB, 2));

        float sumA = 0.f, sumB = 0.f;
        #pragma unroll
        for (int ni = 0; ni < 8; ni++) {
            s[ni][0] = __expf((s[ni][0] - mA) * scale);
            s[ni][1] = __expf((s[ni][1] - mA) * scale);
            s[ni][2] = __expf((s[ni][2] - mB) * scale);
            s[ni][3] = __expf((s[ni][3] - mB) * scale);
            sumA += s[ni][0] + s[ni][1];
            sumB += s[ni][2] + s[ni][3];
        }
        sumA += __shfl_xor_sync(0xffffffff, sumA, 1);
        sumA += __shfl_xor_sync(0xffffffff, sumA, 2);
        sumB += __shfl_xor_sync(0xffffffff, sumB, 1);
        sumB += __shfl_xor_sync(0xffffffff, sumB, 2);
        float invA = 1.f / sumA, invB = 1.f / sumB;

        // ---- normalized half P -> smem ----
        __syncwarp();
        #pragma unroll
        for (int ni = 0; ni < 8; ni++) {
            int col = ni * 8 + c * 2;
            *(half2*)(Ps + g * P_ST + col) =
                __floats2half2_rn(s[ni][0] * invA, s[ni][1] * invA);
            *(half2*)(Ps + (g + 8) * P_ST + col) =
                __floats2half2_rn(s[ni][2] * invB, s[ni][3] * invB);
        }
        __syncwarp();

        // ---- O = P @ V  (m16 x n32, k64: 4 k16 steps) ----
        float o[4][4];
        #pragma unroll
        for (int ni = 0; ni < 4; ni++)
            #pragma unroll
            for (int v = 0; v < 4; v++) o[ni][v] = 0.f;

        #pragma unroll
        for (int ki = 0; ki < 4; ki++) {
            unsigned a0, a1, a2, a3;
            {
                int row = aRowL;
                int col = ki * 16 + aColL;
                ldsm_x4(a0, a1, a2, a3, pSm + (unsigned)((row * P_ST + col) * 2));
            }
            #pragma unroll
            for (int nj = 0; nj < 2; nj++) {
                unsigned b0, b1, b2, b3;
                int row = nj * 16 + bRowL;
                int col = ki * 16 + bColL;
                ldsm_x4(b0, b1, b2, b3, vSm + (unsigned)((row * VT_ST + col) * 2));
                mma_f16(o[2*nj],     a0, a1, a2, a3, b0, b1);
                mma_f16(o[2*nj + 1], a0, a1, a2, a3, b2, b3);
            }
        }

        // ---- store O (half, for GEMM2) ----
        int r0 = mi * 16 + g, r1 = r0 + 8;
        #pragma unroll
        for (int ni = 0; ni < 4; ni++) {
            int col = ni * 8 + c * 2;
            *(half2*)(obh + (size_t)r0 * C_IN + col) =
                __floats2half2_rn(o[ni][0], o[ni][1]);
            *(half2*)(obh + (size_t)r1 * C_IN + col) =
                __floats2half2_rn(o[ni][2], o[ni][3]);
        }
    }
}

extern "C" void kernel_launch(void* const* d_in, const int* in_sizes, int n_in,
                              void* d_out, int out_size)
{
    const float* x      = (const float*)d_in[0];
    const float* w_qkv  = (const float*)d_in[1];
    const float* b_qkv  = (const float*)d_in[2];
    const float* w_proj = (const float*)d_in[3];
    const float* b_proj = (const float*)d_in[4];
    float* out = (float*)d_out;

    __half* d_xc; cudaGetSymbolAddress((void**)&d_xc, g_xc);
    __half* d_wq; cudaGetSymbolAddress((void**)&d_wq, g_wq);
    __half* d_wp; cudaGetSymbolAddress((void**)&d_wp, g_wp);

    cudaFuncSetAttribute(gemm_tc<NQKV, true>,
                         cudaFuncAttributeMaxDynamicSharedMemorySize, SMEM_DYN);
    cudaFuncSetAttribute(gemm_tc<C_IN, false>,
                         cudaFuncAttributeMaxDynamicSharedMemorySize, SMEM_DYN);
    cudaFuncSetAttribute(attn_mma,
                         cudaFuncAttributeMaxDynamicSharedMemorySize, ATT_SMEM);

    // Stage 0: convert x -> half; transpose+convert weights -> [N][K] half
    cvt_half_kernel<<<2048, 256>>>(x, d_xc, NX / 8);
    transpose_half_kernel<<<1728, 256>>>(w_qkv, d_wq, NQKV * C_IN);
    transpose_half_kernel<<<576, 256>>>(w_proj, d_wp, C_IN * C_IN);

    // Stage 1: gathered QKV GEMM (65536 x 1152 x 384), fp16 HMMA + ldmatrix
    gemm_tc<NQKV, true><<<dim3(9, 512), 256, SMEM_DYN>>>(b_qkv, out);

    // Stage 2: window attention via fp16 tensor cores + ldmatrix
    attn_mma<<<3072, 128, ATT_SMEM>>>();

    // Stage 3: proj GEMM with scatter (65536 x 384 x 384), fp16 HMMA + ldmatrix
    gemm_tc<C_IN, false><<<dim3(3, 512), 256, SMEM_DYN>>>(b_proj, out);
}

// round 17
// speedup vs baseline: 3.3099x; 1.1393x over previous
#include <cuda_runtime.h>
#include <cuda_fp16.h>
#include <cstring>

typedef unsigned long long u64;

// Problem constants
#define C_IN   384
#define NQKV   1152
#define MROWS  65536        // 1024 windows * 64 tokens
#define SHIFT_ 4
#define NX     (16*64*64*384)   // 25,165,824

// Scratch (device globals; no allocation in kernel_launch)
__device__ __half g_qkv[(size_t)MROWS * NQKV];   // 151 MB half qkv
__device__ __half g_att[(size_t)MROWS * C_IN];   // 50 MB attention out (half)
__device__ __half g_xc[(size_t)NX];              // 50 MB half x
__device__ __half g_wq[(size_t)NQKV * C_IN];     // w_qkv^T  [N][K] half
__device__ __half g_wp[(size_t)C_IN * C_IN];     // w_proj^T [N][K] half

__device__ __forceinline__ int pix_base(int m) {
    int w  = m >> 6;
    int t  = m & 63;
    int b  = w >> 6;
    int wh = (w >> 3) & 7;
    int ww = w & 7;
    int i  = t >> 3;
    int j  = t & 7;
    int r  = (wh * 8 + i + SHIFT_) & 63;
    int c  = (ww * 8 + j + SHIFT_) & 63;
    return ((b * 64 + r) * 64 + c) * C_IN;
}

__device__ __forceinline__ unsigned h2_bits(half2 h) {
    unsigned u;
    memcpy(&u, &h, 4);
    return u;
}

__device__ __forceinline__ void cp_async16(unsigned dst_smem, const void* src) {
    asm volatile("cp.async.cg.shared.global [%0], [%1], 16;"
                 :: "r"(dst_smem), "l"(src));
}

__device__ __forceinline__ unsigned smem_u32(const void* p) {
    unsigned a;
    asm("{ .reg .u64 t; cvta.to.shared.u64 t, %1; cvt.u32.u64 %0, t; }"
        : "=r"(a) : "l"(p));
    return a;
}

// ldmatrix x4 (non-transposed)
__device__ __forceinline__ void ldsm_x4(unsigned& r0, unsigned& r1,
                                        unsigned& r2, unsigned& r3,
                                        unsigned addr) {
    asm volatile("ldmatrix.sync.aligned.m8n8.x4.shared.b16 {%0,%1,%2,%3}, [%4];"
                 : "=r"(r0), "=r"(r1), "=r"(r2), "=r"(r3) : "r"(addr));
}

// ldmatrix x4 transposed (B fragments from natural [k][n] tiles)
__device__ __forceinline__ void ldsm_x4_t(unsigned& r0, unsigned& r1,
                                          unsigned& r2, unsigned& r3,
                                          unsigned addr) {
    asm volatile("ldmatrix.sync.aligned.m8n8.x4.trans.shared.b16 {%0,%1,%2,%3}, [%4];"
                 : "=r"(r0), "=r"(r1), "=r"(r2), "=r"(r3) : "r"(addr));
}

// fp16 warp MMA m16n8k16, fp32 accumulate
__device__ __forceinline__ void mma_f16(float* d, unsigned a0, unsigned a1,
                                        unsigned a2, unsigned a3,
                                        unsigned b0, unsigned b1) {
    asm volatile(
        "mma.sync.aligned.m16n8k16.row.col.f32.f16.f16.f32 "
        "{%0,%1,%2,%3}, {%4,%5,%6,%7}, {%8,%9}, {%0,%1,%2,%3};"
        : "+f"(d[0]), "+f"(d[1]), "+f"(d[2]), "+f"(d[3])
        : "r"(a0), "r"(a1), "r"(a2), "r"(a3), "r"(b0), "r"(b1));
}

// ---- prep: fp32 -> half elementwise (8 elems/thread-iter) ----
__global__ void cvt_half_kernel(const float* __restrict__ src,
                                __half* __restrict__ dst, int n8)
{
    int i = blockIdx.x * blockDim.x + threadIdx.x;
    int stride = gridDim.x * blockDim.x;
    for (; i < n8; i += stride) {
        float4 a = ((const float4*)src)[2 * i];
        float4 b = ((const float4*)src)[2 * i + 1];
        uint4 o;
        o.x = h2_bits(__floats2half2_rn(a.x, a.y));
        o.y = h2_bits(__floats2half2_rn(a.z, a.w));
        o.z = h2_bits(__floats2half2_rn(b.x, b.y));
        o.w = h2_bits(__floats2half2_rn(b.z, b.w));
        ((uint4*)dst)[i] = o;
    }
}

// ---- prep: transpose + cvt: src fp32 [K=384][N] -> dst half [N][384] ----
__global__ void transpose_half_kernel(const float* __restrict__ src,
                                      __half* __restrict__ dst, int total)
{
    int i = blockIdx.x * blockDim.x + threadIdx.x;
    int stride = gridDim.x * blockDim.x;
    int N = total / C_IN;
    for (; i < total; i += stride) {
        int n = i / C_IN, k = i - n * C_IN;
        dst[i] = __float2half(src[(size_t)k * N + n]);
    }
}

// ---- fp16 GEMM: 128x128 tile, K-chunk 64 halfs, 3-stage cp.async ----
#define KCH  64
#define AST  72
#define BST  72
#define ABUF (128*AST)   // halfs
#define BBUF (128*BST)   // halfs
#define SMEM_DYN ((3*ABUF + 3*BBUF) * 2)   // 110592 bytes

template<int N, bool STAGE1>
__global__ __launch_bounds__(256, 2) void gemm_tc(const float* __restrict__ bias,
                                                  float* __restrict__ Y)
{
    extern __shared__ __half hsm[];
    __half* Asm = hsm;                 // 3 * ABUF
    __half* Bsm = hsm + 3 * ABUF;      // 3 * BBUF
    __shared__ int rowBase[128];
    __shared__ int outBase[128];

    const int tid = threadIdx.x;
    const int m0  = blockIdx.y * 128;
    const int n0  = blockIdx.x * 128;

    if (tid < 128) {
        int m = m0 + tid;
        rowBase[tid] = STAGE1 ? pix_base(m) : m * C_IN;
        if (!STAGE1) outBase[tid] = pix_base(m);
    }
    __syncthreads();

    const __half* Asrc = STAGE1 ? g_xc : g_att;
    const __half* Wt   = STAGE1 ? g_wq : g_wp;

    const int warp = tid >> 5, lane = tid & 31;
    const int wm = warp >> 2;
    const int wn = warp & 3;
    const int g = lane >> 2, c = lane & 3;

    const int sRow = tid >> 3;
    const int sCol = (tid & 7) << 3;

    unsigned aSm = smem_u32(Asm);
    unsigned bSm = smem_u32(Bsm);

    const int aRowL = lane & 15;
    const int aColL = (lane >> 4) << 3;
    const int bRowL = ((lane >> 4) << 3) + (lane & 7);
    const int bColL = ((lane >> 3) & 1) << 3;

    float acc[4][4][4];
    #pragma unroll
    for (int mi = 0; mi < 4; mi++)
        #pragma unroll
        for (int ni = 0; ni < 4; ni++)
            #pragma unroll
            for (int v = 0; v < 4; v++) acc[mi][ni][v] = 0.f;

    const int NIT = C_IN / KCH;   // 6

    auto stage = [&](int chunk, int buf) {
        int k0 = chunk * KCH;
        #pragma unroll
        for (int it = 0; it < 4; it++) {
            int r = sRow + it * 32;
            cp_async16(aSm + (unsigned)((buf * ABUF + r * AST + sCol) * 2),
                       Asrc + rowBase[r] + k0 + sCol);
        }
        #pragma unroll
        for (int it = 0; it < 4; it++) {
            int r = sRow + it * 32;
            cp_async16(bSm + (unsigned)((buf * BBUF + r * BST + sCol) * 2),
                       Wt + (size_t)(n0 + r) * C_IN + k0 + sCol);
        }
        asm volatile("cp.async.commit_group;");
    };

    stage(0, 0);
    stage(1, 1);

    for (int itc = 0; itc < NIT; itc++) {
        if (itc + 1 < NIT) {
            asm volatile("cp.async.wait_group 1;");
        } else {
            asm volatile("cp.async.wait_group 0;");
        }
        __syncthreads();
        if (itc + 2 < NIT) stage(itc + 2, (itc + 2) % 3);

        const unsigned aB = aSm + (unsigned)((itc % 3) * ABUF * 2);
        const unsigned bB = bSm + (unsigned)((itc % 3) * BBUF * 2);

        #pragma unroll
        for (int ki = 0; ki < 4; ki++) {
            unsigned af[4][4], bf[4][2];
            #pragma unroll
            for (int mi = 0; mi < 4; mi++) {
                int row = wm * 64 + mi * 16 + aRowL;
                int col = ki * 16 + aColL;
                ldsm_x4(af[mi][0], af[mi][1], af[mi][2], af[mi][3],
                        aB + (unsigned)((row * AST + col) * 2));
            }
            #pragma unroll
            for (int nj = 0; nj < 2; nj++) {
                int row = wn * 32 + nj * 16 + bRowL;
                int col = ki * 16 + bColL;
                ldsm_x4(bf[2*nj][0], bf[2*nj][1], bf[2*nj+1][0], bf[2*nj+1][1],
                        bB + (unsigned)((row * BST + col) * 2));
            }
            #pragma unroll
            for (int mi = 0; mi < 4; mi++)
                #pragma unroll
                for (int ni = 0; ni < 4; ni++)
                    mma_f16(acc[mi][ni], af[mi][0], af[mi][1], af[mi][2],
                            af[mi][3], bf[ni][0], bf[ni][1]);
        }
        __syncthreads();
    }

    #pragma unroll
    for (int mi = 0; mi < 4; mi++) {
        int mrow = (wm * 4 + mi) * 16 + g;
        #pragma unroll
        for (int half_ = 0; half_ < 2; half_++) {
            int ml = mrow + half_ * 8;
            #pragma unroll
            for (int ni = 0; ni < 4; ni++) {
                int n = n0 + (wn * 4 + ni) * 8 + c * 2;
                float2 b2 = *(const float2*)(bias + n);
                float vx = acc[mi][ni][half_ * 2 + 0] + b2.x;
                float vy = acc[mi][ni][half_ * 2 + 1] + b2.y;
                if (STAGE1) {
                    size_t ob = (size_t)(m0 + ml) * N;
                    *(half2*)(g_qkv + ob + n) = __floats2half2_rn(vx, vy);
                } else {
                    size_t ob = (size_t)outBase[ml];
                    *(float2*)(Y + ob + n) = make_float2(vx, vy);
                }
            }
        }
    }
}

// ---- fp16 MMA attention: one warp per (window, head), 4 warps/block ----
// Qs[64][40], Ks[64][40], Vs[64][40] natural; Ps[16][72].
// PV B-fragments via ldmatrix.trans on natural Vs (vectorized staging).
#define Q_ST  40
#define K_ST  40
#define V_ST2 40
#define P_ST  72
#define WSLH  (64*Q_ST + 64*K_ST + 64*V_ST2 + 16*P_ST)   // 8832 halfs
#define ATT_SMEM (4 * WSLH * 2)                          // 70656 bytes

__global__ __launch_bounds__(128) void attn_mma()
{
    extern __shared__ __half hsmem[];
    const int warp = threadIdx.x >> 5, lane = threadIdx.x & 31;
    const int id = blockIdx.x * 4 + warp;
    const int w = id / 12, h = id - w * 12;

    __half* Qs = hsmem + warp * WSLH;
    __half* Ks = Qs + 64 * Q_ST;
    __half* Vs = Ks + 64 * K_ST;
    __half* Ps = Vs + 64 * V_ST2;

    unsigned qSm = smem_u32(Qs);
    unsigned kSm = smem_u32(Ks);
    unsigned vSm = smem_u32(Vs);
    unsigned pSm = smem_u32(Ps);

    const __half* base = g_qkv + (size_t)w * 64 * NQKV;
    const int qo = h * 32, ko = 384 + h * 32, vo = 768 + h * 32;

    // vectorized staging of Q, K, V (all natural [tok][d])
    for (int e = lane; e < 256; e += 32) {
        int tok = e >> 2, d8 = (e & 3) << 3;
        *(uint4*)(Qs + tok * Q_ST + d8)  = *(const uint4*)(base + tok * NQKV + qo + d8);
        *(uint4*)(Ks + tok * K_ST + d8)  = *(const uint4*)(base + tok * NQKV + ko + d8);
        *(uint4*)(Vs + tok * V_ST2 + d8) = *(const uint4*)(base + tok * NQKV + vo + d8);
    }
    __syncwarp();

    const int g = lane >> 2, c = lane & 3;
    const int aRowL = lane & 15;
    const int aColL = (lane >> 4) << 3;
    const int bRowL = ((lane >> 4) << 3) + (lane & 7);
    const int bColL = ((lane >> 3) & 1) << 3;
    // trans-ldmatrix coords for V: row(tok) = lane&15, col(d) = (lane>>4)*8
    const int vRowL = lane & 15;
    const int vColL = (lane >> 4) << 3;
    const float scale = 0.17677669529663687f;   // 1/sqrt(32)
    __half* obh = g_att + (size_t)w * 64 * C_IN + h * 32;

    for (int mi = 0; mi < 4; mi++) {
        // ---- S = Q @ K^T  (m16 x n64, k32: 2 k16 steps) ----
        float s[8][4];
        #pragma unroll
        for (int ni = 0; ni < 8; ni++)
            #pragma unroll
            for (int v = 0; v < 4; v++) s[ni][v] = 0.f;

        #pragma unroll
        for (int ki = 0; ki < 2; ki++) {
            unsigned a0, a1, a2, a3;
            {
                int row = mi * 16 + aRowL;
                int col = ki * 16 + aColL;
                ldsm_x4(a0, a1, a2, a3, qSm + (unsigned)((row * Q_ST + col) * 2));
            }
            #pragma unroll
            for (int nj = 0; nj < 4; nj++) {
                unsigned b0, b1, b2, b3;
                int row = nj * 16 + bRowL;
                int col = ki * 16 + bColL;
                ldsm_x4(b0, b1, b2, b3, kSm + (unsigned)((row * K_ST + col) * 2));
                mma_f16(s[2*nj],     a0, a1, a2, a3, b0, b1);
                mma_f16(s[2*nj + 1], a0, a1, a2, a3, b2, b3);
            }
        }

        // ---- softmax over the two rows this thread covers ----
        float mA = -1e30f, mB = -1e30f;
        #pragma unroll
        for (int ni = 0; ni < 8; ni++) {
            mA = fmaxf(mA, fmaxf(s[ni][0], s[ni][1]));
            mB = fmaxf(mB, fmaxf(s[ni][2], s[ni][3]));
        }
        mA = fmaxf(mA, __shfl_xor_sync(0xffffffff, mA, 1));
        mA = fmaxf(mA, __shfl_xor_sync(0xffffffff, mA, 2));
        mB = fmaxf(mB, __shfl_xor_sync(0xffffffff, mB, 1));
        mB = fmaxf(mB, __shfl_xor_sync(0xffffffff, mB, 2));

        float sumA = 0.f, sumB = 0.f;
        #pragma unroll
        for (int ni = 0; ni < 8; ni++) {
            s[ni][0] = __expf((s[ni][0] - mA) * scale);
            s[ni][1] = __expf((s[ni][1] - mA) * scale);
            s[ni][2] = __expf((s[ni][2] - mB) * scale);
            s[ni][3] = __expf((s[ni][3] - mB) * scale);
            sumA += s[ni][0] + s[ni][1];
            sumB += s[ni][2] + s[ni][3];
        }
        sumA += __shfl_xor_sync(0xffffffff, sumA, 1);
        sumA += __shfl_xor_sync(0xffffffff, sumA, 2);
        sumB += __shfl_xor_sync(0xffffffff, sumB, 1);
        sumB += __shfl_xor_sync(0xffffffff, sumB, 2);
        float invA = 1.f / sumA, invB = 1.f / sumB;

        // ---- normalized half P -> smem ----
        __syncwarp();
        #pragma unroll
        for (int ni = 0; ni < 8; ni++) {
            int col = ni * 8 + c * 2;
            *(half2*)(Ps + g * P_ST + col) =
                __floats2half2_rn(s[ni][0] * invA, s[ni][1] * invA);
            *(half2*)(Ps + (g + 8) * P_ST + col) =
                __floats2half2_rn(s[ni][2] * invB, s[ni][3] * invB);
        }
        __syncwarp();

        // ---- O = P @ V  (m16 x n32, k64: 4 k16 steps), trans-ldmatrix B ----
        float o[4][4];
        #pragma unroll
        for (int ni = 0; ni < 4; ni++)
            #pragma unroll
            for (int v = 0; v < 4; v++) o[ni][v] = 0.f;

        #pragma unroll
        for (int ki = 0; ki < 4; ki++) {
            unsigned a0, a1, a2, a3;
            {
                int row = aRowL;
                int col = ki * 16 + aColL;
                ldsm_x4(a0, a1, a2, a3, pSm + (unsigned)((row * P_ST + col) * 2));
            }
            #pragma unroll
            for (int dj = 0; dj < 2; dj++) {
                unsigned b0, b1, b2, b3;
                int row = ki * 16 + vRowL;         // tok
                int col = dj * 16 + vColL;         // d
                ldsm_x4_t(b0, b1, b2, b3, vSm + (unsigned)((row * V_ST2 + col) * 2));
                mma_f16(o[2*dj],     a0, a1, a2, a3, b0, b1);
                mma_f16(o[2*dj + 1], a0, a1, a2, a3, b2, b3);
            }
        }

        // ---- store O (half, for GEMM2) ----
        int r0 = mi * 16 + g, r1 = r0 + 8;
        #pragma unroll
        for (int ni = 0; ni < 4; ni++) {
            int col = ni * 8 + c * 2;
            *(half2*)(obh + (size_t)r0 * C_IN + col) =
                __floats2half2_rn(o[ni][0], o[ni][1]);
            *(half2*)(obh + (size_t)r1 * C_IN + col) =
                __floats2half2_rn(o[ni][2], o[ni][3]);
        }
    }
}

extern "C" void kernel_launch(void* const* d_in, const int* in_sizes, int n_in,
                              void* d_out, int out_size)
{
    const float* x      = (const float*)d_in[0];
    const float* w_qkv  = (const float*)d_in[1];
    const float* b_qkv  = (const float*)d_in[2];
    const float* w_proj = (const float*)d_in[3];
    const float* b_proj = (const float*)d_in[4];
    float* out = (float*)d_out;

    __half* d_xc; cudaGetSymbolAddress((void**)&d_xc, g_xc);
    __half* d_wq; cudaGetSymbolAddress((void**)&d_wq, g_wq);
    __half* d_wp; cudaGetSymbolAddress((void**)&d_wp, g_wp);

    cudaFuncSetAttribute(gemm_tc<NQKV, true>,
                         cudaFuncAttributeMaxDynamicSharedMemorySize, SMEM_DYN);
    cudaFuncSetAttribute(gemm_tc<C_IN, false>,
                         cudaFuncAttributeMaxDynamicSharedMemorySize, SMEM_DYN);
    cudaFuncSetAttribute(attn_mma,
                         cudaFuncAttributeMaxDynamicSharedMemorySize, ATT_SMEM);

    // Stage 0: convert x -> half; transpose+convert weights -> [N][K] half
    cvt_half_kernel<<<2048, 256>>>(x, d_xc, NX / 8);
    transpose_half_kernel<<<1728, 256>>>(w_qkv, d_wq, NQKV * C_IN);
    transpose_half_kernel<<<576, 256>>>(w_proj, d_wp, C_IN * C_IN);

    // Stage 1: gathered QKV GEMM (65536 x 1152 x 384), fp16 HMMA, 3-stage
    gemm_tc<NQKV, true><<<dim3(9, 512), 256, SMEM_DYN>>>(b_qkv, out);

    // Stage 2: window attention, fp16 MMA + trans-ldmatrix V
    attn_mma<<<3072, 128, ATT_SMEM>>>();

    // Stage 3: proj GEMM with scatter (65536 x 384 x 384), fp16 HMMA, 3-stage
    gemm_tc<C_IN, false><<<dim3(3, 512), 256, SMEM_DYN>>>(b_proj, out);
}